// round 7
// baseline (speedup 1.0000x reference)
#include <cuda_runtime.h>
#include <cuda_bf16.h>
#include <cstdint>
#include <math.h>

// Problem constants
constexpr int B_ = 4, S_ = 2048, E_ = 1024, H_ = 16, D_ = 64;
constexpr int M_ = B_ * S_;            // 8192 rows
constexpr int NKQV = 3 * E_;           // 3072

// ---------------------------------------------------------------------------
// Scratch (device globals; bf16 hi/lo pairs)
// ---------------------------------------------------------------------------
__device__ __nv_bfloat16 g_xh[(size_t)M_ * E_],  g_xl[(size_t)M_ * E_];
__device__ __nv_bfloat16 g_wkh[(size_t)NKQV * E_], g_wkl[(size_t)NKQV * E_];
__device__ __nv_bfloat16 g_wph[(size_t)E_ * E_], g_wpl[(size_t)E_ * E_];
__device__ __nv_bfloat16 g_qh[(size_t)B_*H_*S_*D_], g_ql[(size_t)B_*H_*S_*D_];
__device__ __nv_bfloat16 g_kh[(size_t)B_*H_*S_*D_], g_kl[(size_t)B_*H_*S_*D_];
__device__ __nv_bfloat16 g_vh[(size_t)B_*H_*S_*D_], g_vl[(size_t)B_*H_*S_*D_];
__device__ __nv_bfloat16 g_vth[(size_t)B_*H_*S_*D_], g_vtl[(size_t)B_*H_*S_*D_];
__device__ __nv_bfloat16 g_yh[(size_t)M_ * E_],  g_yl[(size_t)M_ * E_];

// ---------------------------------------------------------------------------
// helpers
// ---------------------------------------------------------------------------
__device__ __forceinline__ uint32_t pack_bf16x2(float a, float b) {
    __nv_bfloat16 ha = __float2bfloat16_rn(a);
    __nv_bfloat16 hb = __float2bfloat16_rn(b);
    return (uint32_t)__bfloat16_as_ushort(ha) |
           ((uint32_t)__bfloat16_as_ushort(hb) << 16);
}
__device__ __forceinline__ float bf16_resid(float a) {
    return a - __bfloat162float(__float2bfloat16_rn(a));
}

__device__ __forceinline__ void mma16816(float* c, const uint32_t* a,
                                         uint32_t b0, uint32_t b1) {
    asm volatile(
        "mma.sync.aligned.m16n8k16.row.col.f32.bf16.bf16.f32 "
        "{%0,%1,%2,%3}, {%4,%5,%6,%7}, {%8,%9}, {%0,%1,%2,%3};"
        : "+f"(c[0]), "+f"(c[1]), "+f"(c[2]), "+f"(c[3])
        : "r"(a[0]), "r"(a[1]), "r"(a[2]), "r"(a[3]), "r"(b0), "r"(b1));
}

__device__ __forceinline__ void ldsm_x4(uint32_t* r, uint32_t addr) {
    asm volatile(
        "ldmatrix.sync.aligned.m8n8.x4.shared.b16 {%0,%1,%2,%3}, [%4];"
        : "=r"(r[0]), "=r"(r[1]), "=r"(r[2]), "=r"(r[3]) : "r"(addr));
}

__device__ __forceinline__ uint32_t smem_u32(const void* p) {
    uint32_t a;
    asm("{ .reg .u64 t; cvta.to.shared.u64 t, %1; cvt.u32.u64 %0, t; }"
        : "=r"(a) : "l"(p));
    return a;
}
__device__ __forceinline__ void cp16(uint32_t dst, const void* src) {
    asm volatile("cp.async.ca.shared.global [%0], [%1], 16;"
                 :: "r"(dst), "l"(src));
}
#define CP_COMMIT() asm volatile("cp.async.commit_group;" ::: "memory")
#define CP_WAIT1()  asm volatile("cp.async.wait_group 1;" ::: "memory")
#define CP_WAIT0()  asm volatile("cp.async.wait_group 0;" ::: "memory")

// FMA-pipe exp2 (input in log2 units). ~2e-6 rel err.
__device__ __forceinline__ float exp2p(float x) {
    x = fmaxf(x, -80.f);
    float t = x + 12582912.f;
    int n = __float_as_int(t) - 0x4B400000;
    float r = x - (t - 12582912.f);
    float p = 1.33335581e-3f;
    p = fmaf(p, r, 9.61812911e-3f);
    p = fmaf(p, r, 5.55041087e-2f);
    p = fmaf(p, r, 2.40226507e-1f);
    p = fmaf(p, r, 6.93147180e-1f);
    p = fmaf(p, r, 1.0f);
    return p * __int_as_float((n + 127) << 23);
}

constexpr float QSCALE = 0.125f * 1.44269504088896340736f;

// ---------------------------------------------------------------------------
// split: fp32 -> bf16 hi + lo
// ---------------------------------------------------------------------------
__global__ void split_kernel(const float* __restrict__ src,
                             __nv_bfloat16* __restrict__ hi,
                             __nv_bfloat16* __restrict__ lo, int n4) {
    int i = blockIdx.x * blockDim.x + threadIdx.x;
    if (i >= n4) return;
    float4 v = ((const float4*)src)[i];
    ((uint2*)hi)[i] = make_uint2(pack_bf16x2(v.x, v.y), pack_bf16x2(v.z, v.w));
    ((uint2*)lo)[i] = make_uint2(
        pack_bf16x2(bf16_resid(v.x), bf16_resid(v.y)),
        pack_bf16x2(bf16_resid(v.z), bf16_resid(v.w)));
}

// ---------------------------------------------------------------------------
// GEMM: C[M,N] = (Ah+Al)[M,K] @ (Bh+Bl)[N,K]^T + bias
// 256x128x32 CTA tile, 8 warps of 64x64, 3-stage cp.async pipeline,
// ldmatrix fragments, split-major MMA issue order. 1 CTA/SM.
// MODE 0: fp32 row-major C.  MODE 1: bf16 hi/lo scatter to q/k/v buffers.
// ---------------------------------------------------------------------------
constexpr int GBK = 32;
constexpr int GSTR = 40;                     // padded bf16 stride (80B rows)
constexpr int GTA_E = 256 * GSTR;            // A tile: 10240 elems per split
constexpr int GTB_E = 128 * GSTR;            // B tile: 5120 elems per split
constexpr int GSTAGE_E = 2 * GTA_E + 2 * GTB_E;   // 30720
constexpr int GSMEM = 3 * GSTAGE_E * 2;      // 184320 B

template <int MODE>
__global__ __launch_bounds__(256, 1) void gemm_cp(
    const __nv_bfloat16* __restrict__ Ah, const __nv_bfloat16* __restrict__ Al,
    const __nv_bfloat16* __restrict__ Bh, const __nv_bfloat16* __restrict__ Bl,
    const float* __restrict__ bias, float* __restrict__ C,
    int M, int N, int K)
{
    extern __shared__ __nv_bfloat16 smb[];
    const uint32_t smb_u = smem_u32(smb);
    const int tid = threadIdx.x;
    const int lane = tid & 31;
    const int w = tid >> 5;
    const int wm = w & 3, wn = w >> 2;    // 4 m-warps x 2 n-warps
    const int g = lane >> 2, t = lane & 3;
    const int m0 = blockIdx.y * 256;
    const int n0 = blockIdx.x * 128;

    const __nv_bfloat16* Abase[2] = { Ah + (size_t)m0 * K, Al + (size_t)m0 * K };
    const __nv_bfloat16* Bbase[2] = { Bh + (size_t)n0 * K, Bl + (size_t)n0 * K };

    const int nsteps = K / GBK;          // 32

    auto issue = [&](int s) {
        __nv_bfloat16* st = smb + (s % 3) * GSTAGE_E;
        const int k0 = s * GBK;
        // A: c = 0..7 (2048 chunks), B: c = 8..11 (1024 chunks)
#pragma unroll
        for (int c = 0; c < 8; c++) {
            int ci = tid + c * 256;
            int split = ci >> 10;            // 0..1
            int idx = ci & 1023;
            int r = idx >> 2, ch = idx & 3;
            cp16(smem_u32(st + split * GTA_E + r * GSTR + ch * 8),
                 Abase[split] + (size_t)r * K + k0 + ch * 8);
        }
#pragma unroll
        for (int c = 0; c < 4; c++) {
            int ci = tid + c * 256;
            int split = ci >> 9;             // 0..1
            int idx = ci & 511;
            int r = idx >> 2, ch = idx & 3;
            cp16(smem_u32(st + 2 * GTA_E + split * GTB_E + r * GSTR + ch * 8),
                 Bbase[split] + (size_t)r * K + k0 + ch * 8);
        }
        CP_COMMIT();
    };

    const uint32_t a_off =
        (uint32_t)((wm * 64 + (lane & 15)) * GSTR + (lane >> 4) * 8) * 2;
    const uint32_t b_off =
        (uint32_t)((wn * 64 + ((lane >> 4) & 1) * 8 + (lane & 7)) * GSTR +
                   ((lane >> 3) & 1) * 8) * 2;

    float acc[4][8][4];
#pragma unroll
    for (int i = 0; i < 4; i++)
#pragma unroll
        for (int j = 0; j < 8; j++)
#pragma unroll
            for (int e = 0; e < 4; e++) acc[i][j][e] = 0.f;

    issue(0);
    issue(1);

    for (int s = 0; s < nsteps; s++) {
        if (s + 1 < nsteps) { CP_WAIT1(); } else { CP_WAIT0(); }
        __syncthreads();
        if (s + 2 < nsteps) issue(s + 2);   // 3 buffers: (s+2)%3 free

        const uint32_t st = smb_u + (uint32_t)((s % 3) * GSTAGE_E) * 2;
        const uint32_t uAh = st;
        const uint32_t uAl = st + GTA_E * 2;
        const uint32_t uBh = st + 2 * GTA_E * 2;
        const uint32_t uBl = st + 2 * GTA_E * 2 + GTB_E * 2;

#pragma unroll
        for (int ks = 0; ks < 2; ks++) {
            const uint32_t kso = (uint32_t)(ks * 16) * 2;
            uint32_t ah[4][4], al[4][4];
#pragma unroll
            for (int mt = 0; mt < 4; mt++) {
                const uint32_t ro = (uint32_t)(mt * 16 * GSTR) * 2;
                ldsm_x4(ah[mt], uAh + a_off + ro + kso);
                ldsm_x4(al[mt], uAl + a_off + ro + kso);
            }
#pragma unroll
            for (int p = 0; p < 4; p++) {    // 4 n-pairs of 16 cols
                const uint32_t ro = (uint32_t)(p * 16 * GSTR) * 2;
                uint32_t bh[4], bl[4];
                ldsm_x4(bh, uBh + b_off + ro + kso);
                ldsm_x4(bl, uBl + b_off + ro + kso);
                // split-major issue: accumulator reuse distance 4
#pragma unroll
                for (int mt = 0; mt < 4; mt++)
                    mma16816(acc[mt][2 * p], ah[mt], bh[0], bh[1]);
#pragma unroll
                for (int mt = 0; mt < 4; mt++)
                    mma16816(acc[mt][2 * p + 1], ah[mt], bh[2], bh[3]);
#pragma unroll
                for (int mt = 0; mt < 4; mt++)
                    mma16816(acc[mt][2 * p], al[mt], bh[0], bh[1]);
#pragma unroll
                for (int mt = 0; mt < 4; mt++)
                    mma16816(acc[mt][2 * p + 1], al[mt], bh[2], bh[3]);
#pragma unroll
                for (int mt = 0; mt < 4; mt++)
                    mma16816(acc[mt][2 * p], ah[mt], bl[0], bl[1]);
#pragma unroll
                for (int mt = 0; mt < 4; mt++)
                    mma16816(acc[mt][2 * p + 1], ah[mt], bl[2], bl[3]);
            }
        }
    }

    // ---- epilogue --------------------------------------------------------
#pragma unroll
    for (int mt = 0; mt < 4; mt++) {
#pragma unroll
        for (int nt = 0; nt < 8; nt++) {
            const int m = m0 + wm * 64 + mt * 16 + g;
            const int n = n0 + wn * 64 + nt * 8 + t * 2;
            const float* c = acc[mt][nt];
            float2 bv = *(const float2*)(bias + n);
            if (MODE == 0) {
                *(float2*)(C + (size_t)m * N + n) =
                    make_float2(c[0] + bv.x, c[1] + bv.y);
                *(float2*)(C + (size_t)(m + 8) * N + n) =
                    make_float2(c[2] + bv.x, c[3] + bv.y);
            } else {
                const int which = n >> 10;
                const int h = (n >> 6) & 15;
                const int d = n & 63;
                const float sc = (which == 1) ? QSCALE : 1.0f;
                __nv_bfloat16* dh = (which == 0 ? g_kh : which == 1 ? g_qh : g_vh);
                __nv_bfloat16* dl = (which == 0 ? g_kl : which == 1 ? g_ql : g_vl);
#pragma unroll
                for (int rr = 0; rr < 2; rr++) {
                    const int mm = m + rr * 8;
                    const int b = mm >> 11, s = mm & 2047;
                    const size_t off =
                        ((((size_t)b * H_ + h) * S_) + s) * D_ + d;
                    float v0 = (c[rr * 2 + 0] + bv.x) * sc;
                    float v1 = (c[rr * 2 + 1] + bv.y) * sc;
                    *(uint32_t*)(dh + off) = pack_bf16x2(v0, v1);
                    *(uint32_t*)(dl + off) =
                        pack_bf16x2(bf16_resid(v0), bf16_resid(v1));
                }
            }
        }
    }
}

// ---------------------------------------------------------------------------
// V transpose: [bh][s][d] -> [bh][d][s], hi and lo
// ---------------------------------------------------------------------------
__global__ __launch_bounds__(256) void vtrans_kernel() {
    __shared__ __nv_bfloat16 tile[64][72];
    const int tid = threadIdx.x;
    const int st = blockIdx.x;
    const int bh = blockIdx.y;

    const __nv_bfloat16* srcs[2] = {
        g_vh + ((size_t)bh * S_ + st * 64) * D_,
        g_vl + ((size_t)bh * S_ + st * 64) * D_ };
    __nv_bfloat16* dsts[2] = {
        g_vth + (size_t)bh * D_ * S_ + st * 64,
        g_vtl + (size_t)bh * D_ * S_ + st * 64 };

    for (int a = 0; a < 2; a++) {
        __syncthreads();
#pragma unroll
        for (int c = 0; c < 8; c++) {
            int ci = tid + c * 256;
            int r = ci >> 5, ch = ci & 31;
            *(uint32_t*)&tile[r][ch * 2] =
                *(const uint32_t*)(srcs[a] + (size_t)r * D_ + ch * 2);
        }
        __syncthreads();
#pragma unroll
        for (int c = 0; c < 8; c++) {
            int ci = tid + c * 256;
            int d = ci >> 5, s2 = (ci & 31) * 2;
            uint32_t o = (uint32_t)__bfloat16_as_ushort(tile[s2][d]) |
                         ((uint32_t)__bfloat16_as_ushort(tile[s2 + 1][d]) << 16);
            *(uint32_t*)(dsts[a] + (size_t)d * S_ + s2) = o;
        }
    }
}

// ---------------------------------------------------------------------------
// Tensor-core causal flash attention. CTA = (q-tile 128, bh), 8 warps.
// K-tiles of 64; 3-buffer cp.async prefetch 2 ahead; ldmatrix fragments with
// hoisted loads + split-major MMA order; FMA-pipe exp2. (unchanged from R6)
// ---------------------------------------------------------------------------
constexpr int ASTR = 72;
constexpr int AQ_E = 2 * 128 * ASTR;
constexpr int AKT_E = 64 * ASTR;
constexpr int AKSTAGE_E = 4 * AKT_E;
constexpr int ASMEM = (AQ_E + 3 * AKSTAGE_E) * 2;   // 147456 B

__global__ __launch_bounds__(256) void attn_mma() {
    extern __shared__ __nv_bfloat16 sma[];
    const uint32_t sma_u = smem_u32(sma);
    const int tid = threadIdx.x;
    const int lane = tid & 31;
    const int w = tid >> 5;
    const int g = lane >> 2, t = lane & 3;
    const int qt = (S_ / 128 - 1) - blockIdx.x;
    const int bh = blockIdx.y;
    const int nkt = 2 * qt + 2;

    __nv_bfloat16* QH = sma;
    __nv_bfloat16* QL = sma + 128 * ASTR;
    const uint32_t KV0_u = sma_u + AQ_E * 2;

    // ---- stage Q
    {
        const __nv_bfloat16* qsrc[2] = {
            g_qh + ((size_t)bh * S_ + qt * 128) * D_,
            g_ql + ((size_t)bh * S_ + qt * 128) * D_ };
#pragma unroll
        for (int c = 0; c < 8; c++) {
            int ci = tid + c * 256;
            int arr = ci >> 10;
            int idx = ci & 1023;
            int r = idx >> 3, ch = idx & 7;
            cp16(smem_u32(sma + arr * (128 * ASTR) + r * ASTR + ch * 8),
                 qsrc[arr] + (size_t)r * D_ + ch * 8);
        }
        CP_COMMIT();
    }

    auto issueKV = [&](int kt) {
        uint32_t st = KV0_u + (uint32_t)((kt % 3) * AKSTAGE_E) * 2;
        const __nv_bfloat16* bases[4] = {
            g_kh + ((size_t)bh * S_ + kt * 64) * D_,
            g_kl + ((size_t)bh * S_ + kt * 64) * D_,
            g_vth + (size_t)bh * D_ * S_ + kt * 64,
            g_vtl + (size_t)bh * D_ * S_ + kt * 64 };
#pragma unroll
        for (int c = 0; c < 8; c++) {
            int ci = tid + c * 256;
            int arr = ci >> 9;
            int idx = ci & 511;
            int r = idx >> 3, ch = idx & 7;
            const size_t rs = (arr < 2) ? (size_t)D_ : (size_t)S_;
            cp16(st + (uint32_t)(arr * AKT_E + r * ASTR + ch * 8) * 2,
                 bases[arr] + (size_t)r * rs + ch * 8);
        }
        CP_COMMIT();
    };

    issueKV(0);
    CP_WAIT1();
    __syncthreads();

    uint32_t qfh[4][4], qfl[4][4];
#pragma unroll
    for (int ks = 0; ks < 4; ks++) {
        const int kb = ks * 16 + t * 2;
        const int r0 = (w * 16 + g) * ASTR;
        qfh[ks][0] = *(const uint32_t*)(QH + r0 + kb);
        qfh[ks][1] = *(const uint32_t*)(QH + r0 + 8 * ASTR + kb);
        qfh[ks][2] = *(const uint32_t*)(QH + r0 + kb + 8);
        qfh[ks][3] = *(const uint32_t*)(QH + r0 + 8 * ASTR + kb + 8);
        qfl[ks][0] = *(const uint32_t*)(QL + r0 + kb);
        qfl[ks][1] = *(const uint32_t*)(QL + r0 + 8 * ASTR + kb);
        qfl[ks][2] = *(const uint32_t*)(QL + r0 + kb + 8);
        qfl[ks][3] = *(const uint32_t*)(QL + r0 + 8 * ASTR + kb + 8);
    }

    issueKV(1);

    const uint32_t bfrag_off =
        (uint32_t)((((lane >> 4) & 1) * 8 + (lane & 7)) * ASTR +
                   ((lane >> 3) & 1) * 8) * 2;

    float o[8][4];
#pragma unroll
    for (int nt = 0; nt < 8; nt++)
#pragma unroll
        for (int e = 0; e < 4; e++) o[nt][e] = 0.f;
    float m0 = -1e30f, m1 = -1e30f, l0 = 0.f, l1 = 0.f;

    const int row0 = qt * 128 + w * 16 + g;
    const int row1 = row0 + 8;

    for (int kt = 0; kt < nkt; kt++) {
        if (kt + 1 < nkt) { CP_WAIT1(); } else { CP_WAIT0(); }
        __syncthreads();
        if (kt + 2 < nkt) issueKV(kt + 2);

        const uint32_t st = KV0_u + (uint32_t)((kt % 3) * AKSTAGE_E) * 2;
        const uint32_t uKH = st;
        const uint32_t uKL = st + AKT_E * 2;
        const uint32_t uVH = st + 2 * AKT_E * 2;
        const uint32_t uVL = st + 3 * AKT_E * 2;

        float sc[8][4];
#pragma unroll
        for (int nt = 0; nt < 8; nt++)
#pragma unroll
            for (int e = 0; e < 4; e++) sc[nt][e] = 0.f;

#pragma unroll
        for (int ks = 0; ks < 4; ks++) {
            const uint32_t kso = (uint32_t)(ks * 16) * 2;
            uint32_t kh4[4][4], kl4[4][4];
#pragma unroll
            for (int ntp = 0; ntp < 4; ntp++) {
                const uint32_t ro = (uint32_t)(ntp * 16 * ASTR) * 2;
                ldsm_x4(kh4[ntp], uKH + bfrag_off + ro + kso);
                ldsm_x4(kl4[ntp], uKL + bfrag_off + ro + kso);
            }
#pragma unroll
            for (int ntp = 0; ntp < 4; ntp++) {
                mma16816(sc[2 * ntp],     qfh[ks], kh4[ntp][0], kh4[ntp][1]);
                mma16816(sc[2 * ntp + 1], qfh[ks], kh4[ntp][2], kh4[ntp][3]);
            }
#pragma unroll
            for (int ntp = 0; ntp < 4; ntp++) {
                mma16816(sc[2 * ntp],     qfl[ks], kh4[ntp][0], kh4[ntp][1]);
                mma16816(sc[2 * ntp + 1], qfl[ks], kh4[ntp][2], kh4[ntp][3]);
            }
#pragma unroll
            for (int ntp = 0; ntp < 4; ntp++) {
                mma16816(sc[2 * ntp],     qfh[ks], kl4[ntp][0], kl4[ntp][1]);
                mma16816(sc[2 * ntp + 1], qfh[ks], kl4[ntp][2], kl4[ntp][3]);
            }
        }

        if (kt >= 2 * qt) {
#pragma unroll
            for (int nt = 0; nt < 8; nt++) {
                const int c0 = kt * 64 + nt * 8 + 2 * t;
                if (c0 > row0)     sc[nt][0] = -1e30f;
                if (c0 + 1 > row0) sc[nt][1] = -1e30f;
                if (c0 > row1)     sc[nt][2] = -1e30f;
                if (c0 + 1 > row1) sc[nt][3] = -1e30f;
            }
        }

        float mx0 = -1e30f, mx1 = -1e30f;
#pragma unroll
        for (int nt = 0; nt < 8; nt++) {
            mx0 = fmaxf(mx0, fmaxf(sc[nt][0], sc[nt][1]));
            mx1 = fmaxf(mx1, fmaxf(sc[nt][2], sc[nt][3]));
        }
        mx0 = fmaxf(mx0, __shfl_xor_sync(0xffffffffu, mx0, 1));
        mx0 = fmaxf(mx0, __shfl_xor_sync(0xffffffffu, mx0, 2));
        mx1 = fmaxf(mx1, __shfl_xor_sync(0xffffffffu, mx1, 1));
        mx1 = fmaxf(mx1, __shfl_xor_sync(0xffffffffu, mx1, 2));

        const float mn0 = fmaxf(m0, mx0), mn1 = fmaxf(m1, mx1);
        const float a0 = exp2p(m0 - mn0), a1 = exp2p(m1 - mn1);
        m0 = mn0; m1 = mn1;

        float rs0 = 0.f, rs1 = 0.f;
#pragma unroll
        for (int nt = 0; nt < 8; nt++) {
            sc[nt][0] = exp2p(sc[nt][0] - mn0);
            sc[nt][1] = exp2p(sc[nt][1] - mn0);
            sc[nt][2] = exp2p(sc[nt][2] - mn1);
            sc[nt][3] = exp2p(sc[nt][3] - mn1);
            rs0 += sc[nt][0] + sc[nt][1];
            rs1 += sc[nt][2] + sc[nt][3];
        }
        rs0 += __shfl_xor_sync(0xffffffffu, rs0, 1);
        rs0 += __shfl_xor_sync(0xffffffffu, rs0, 2);
        rs1 += __shfl_xor_sync(0xffffffffu, rs1, 1);
        rs1 += __shfl_xor_sync(0xffffffffu, rs1, 2);
        l0 = l0 * a0 + rs0;
        l1 = l1 * a1 + rs1;

#pragma unroll
        for (int nt = 0; nt < 8; nt++) {
            o[nt][0] *= a0; o[nt][1] *= a0;
            o[nt][2] *= a1; o[nt][3] *= a1;
        }

        uint32_t pfh[4][4], pfl[4][4];
#pragma unroll
        for (int ks = 0; ks < 4; ks++) {
            const float* p0 = sc[2 * ks];
            const float* p1 = sc[2 * ks + 1];
            pfh[ks][0] = pack_bf16x2(p0[0], p0[1]);
            pfh[ks][1] = pack_bf16x2(p0[2], p0[3]);
            pfh[ks][2] = pack_bf16x2(p1[0], p1[1]);
            pfh[ks][3] = pack_bf16x2(p1[2], p1[3]);
            pfl[ks][0] = pack_bf16x2(bf16_resid(p0[0]), bf16_resid(p0[1]));
            pfl[ks][1] = pack_bf16x2(bf16_resid(p0[2]), bf16_resid(p0[3]));
            pfl[ks][2] = pack_bf16x2(bf16_resid(p1[0]), bf16_resid(p1[1]));
            pfl[ks][3] = pack_bf16x2(bf16_resid(p1[2]), bf16_resid(p1[3]));
        }

#pragma unroll
        for (int ks = 0; ks < 4; ks++) {
            const uint32_t kso = (uint32_t)(ks * 16) * 2;
            uint32_t vh4[4][4], vl4[4][4];
#pragma unroll
            for (int ntp = 0; ntp < 4; ntp++) {
                const uint32_t ro = (uint32_t)(ntp * 16 * ASTR) * 2;
                ldsm_x4(vh4[ntp], uVH + bfrag_off + ro + kso);
                ldsm_x4(vl4[ntp], uVL + bfrag_off + ro + kso);
            }
#pragma unroll
            for (int ntp = 0; ntp < 4; ntp++) {
                mma16816(o[2 * ntp],     pfh[ks], vh4[ntp][0], vh4[ntp][1]);
                mma16816(o[2 * ntp + 1], pfh[ks], vh4[ntp][2], vh4[ntp][3]);
            }
#pragma unroll
            for (int ntp = 0; ntp < 4; ntp++) {
                mma16816(o[2 * ntp],     pfl[ks], vh4[ntp][0], vh4[ntp][1]);
                mma16816(o[2 * ntp + 1], pfl[ks], vh4[ntp][2], vh4[ntp][3]);
            }
#pragma unroll
            for (int ntp = 0; ntp < 4; ntp++) {
                mma16816(o[2 * ntp],     pfh[ks], vl4[ntp][0], vl4[ntp][1]);
                mma16816(o[2 * ntp + 1], pfh[ks], vl4[ntp][2], vl4[ntp][3]);
            }
        }
    }

    const float inv0 = 1.0f / l0, inv1 = 1.0f / l1;
    const int b = bh >> 4, h = bh & 15;
#pragma unroll
    for (int nt = 0; nt < 8; nt++) {
        const int e = h * 64 + nt * 8 + 2 * t;
        {
            const size_t off = ((size_t)b * S_ + row0) * E_ + e;
            float v0 = o[nt][0] * inv0, v1 = o[nt][1] * inv0;
            *(uint32_t*)(g_yh + off) = pack_bf16x2(v0, v1);
            *(uint32_t*)(g_yl + off) =
                pack_bf16x2(bf16_resid(v0), bf16_resid(v1));
        }
        {
            const size_t off = ((size_t)b * S_ + row1) * E_ + e;
            float v0 = o[nt][2] * inv1, v1 = o[nt][3] * inv1;
            *(uint32_t*)(g_yh + off) = pack_bf16x2(v0, v1);
            *(uint32_t*)(g_yl + off) =
                pack_bf16x2(bf16_resid(v0), bf16_resid(v1));
        }
    }
}

// ---------------------------------------------------------------------------
// Launch
// ---------------------------------------------------------------------------
extern "C" void kernel_launch(void* const* d_in, const int* in_sizes, int n_in,
                              void* d_out, int out_size)
{
    const float* x      = (const float*)d_in[0];
    const float* W_kqv  = (const float*)d_in[1];
    const float* b_kqv  = (const float*)d_in[2];
    const float* W_proj = (const float*)d_in[3];
    const float* b_proj = (const float*)d_in[4];
    float* out = (float*)d_out;

    void *xh, *xl, *wkh, *wkl, *wph, *wpl, *yh, *yl;
    cudaGetSymbolAddress(&xh, g_xh);   cudaGetSymbolAddress(&xl, g_xl);
    cudaGetSymbolAddress(&wkh, g_wkh); cudaGetSymbolAddress(&wkl, g_wkl);
    cudaGetSymbolAddress(&wph, g_wph); cudaGetSymbolAddress(&wpl, g_wpl);
    cudaGetSymbolAddress(&yh, g_yh);   cudaGetSymbolAddress(&yl, g_yl);

    cudaFuncSetAttribute(gemm_cp<0>, cudaFuncAttributeMaxDynamicSharedMemorySize, GSMEM);
    cudaFuncSetAttribute(gemm_cp<1>, cudaFuncAttributeMaxDynamicSharedMemorySize, GSMEM);
    cudaFuncSetAttribute(attn_mma,   cudaFuncAttributeMaxDynamicSharedMemorySize, ASMEM);

    // 0) split inputs to bf16 hi/lo
    {
        int n4 = M_ * E_ / 4;
        split_kernel<<<(n4 + 255) / 256, 256>>>(
            x, (__nv_bfloat16*)xh, (__nv_bfloat16*)xl, n4);
        n4 = NKQV * E_ / 4;
        split_kernel<<<(n4 + 255) / 256, 256>>>(
            W_kqv, (__nv_bfloat16*)wkh, (__nv_bfloat16*)wkl, n4);
        n4 = E_ * E_ / 4;
        split_kernel<<<(n4 + 255) / 256, 256>>>(
            W_proj, (__nv_bfloat16*)wph, (__nv_bfloat16*)wpl, n4);
    }

    // 1) QKV projection -> q/k/v bf16 hi/lo (q pre-scaled)
    gemm_cp<1><<<dim3(NKQV / 128, M_ / 256), 256, GSMEM>>>(
        (const __nv_bfloat16*)xh, (const __nv_bfloat16*)xl,
        (const __nv_bfloat16*)wkh, (const __nv_bfloat16*)wkl,
        b_kqv, nullptr, M_, NKQV, E_);

    // 2) V transpose [bh][s][d] -> [bh][d][s]
    vtrans_kernel<<<dim3(S_ / 64, B_ * H_), 256>>>();

    // 3) Tensor-core causal flash attention -> y bf16 hi/lo
    attn_mma<<<dim3(S_ / 128, B_ * H_), 256, ASMEM>>>();

    // 4) Output projection -> d_out (fp32)
    gemm_cp<0><<<dim3(E_ / 128, M_ / 256), 256, GSMEM>>>(
        (const __nv_bfloat16*)yh, (const __nv_bfloat16*)yl,
        (const __nv_bfloat16*)wph, (const __nv_bfloat16*)wpl,
        b_proj, out, M_, E_, E_);
}

// round 8
// speedup vs baseline: 1.0274x; 1.0274x over previous
#include <cuda_runtime.h>
#include <cuda_bf16.h>
#include <cstdint>
#include <math.h>

// Problem constants
constexpr int B_ = 4, S_ = 2048, E_ = 1024, H_ = 16, D_ = 64;
constexpr int M_ = B_ * S_;            // 8192 rows
constexpr int NKQV = 3 * E_;           // 3072

// ---------------------------------------------------------------------------
// Scratch (device globals; bf16 hi/lo pairs)
// ---------------------------------------------------------------------------
__device__ __nv_bfloat16 g_xh[(size_t)M_ * E_],  g_xl[(size_t)M_ * E_];
__device__ __nv_bfloat16 g_wkh[(size_t)NKQV * E_], g_wkl[(size_t)NKQV * E_];
__device__ __nv_bfloat16 g_wph[(size_t)E_ * E_], g_wpl[(size_t)E_ * E_];
__device__ __nv_bfloat16 g_qh[(size_t)B_*H_*S_*D_], g_ql[(size_t)B_*H_*S_*D_];
__device__ __nv_bfloat16 g_kh[(size_t)B_*H_*S_*D_], g_kl[(size_t)B_*H_*S_*D_];
__device__ __nv_bfloat16 g_vh[(size_t)B_*H_*S_*D_], g_vl[(size_t)B_*H_*S_*D_];
__device__ __nv_bfloat16 g_vth[(size_t)B_*H_*S_*D_], g_vtl[(size_t)B_*H_*S_*D_];
__device__ __nv_bfloat16 g_yh[(size_t)M_ * E_],  g_yl[(size_t)M_ * E_];

// ---------------------------------------------------------------------------
// helpers
// ---------------------------------------------------------------------------
__device__ __forceinline__ uint32_t pack_bf16x2(float a, float b) {
    __nv_bfloat16 ha = __float2bfloat16_rn(a);
    __nv_bfloat16 hb = __float2bfloat16_rn(b);
    return (uint32_t)__bfloat16_as_ushort(ha) |
           ((uint32_t)__bfloat16_as_ushort(hb) << 16);
}
__device__ __forceinline__ float bf16_resid(float a) {
    return a - __bfloat162float(__float2bfloat16_rn(a));
}

__device__ __forceinline__ void mma16816(float* c, const uint32_t* a,
                                         uint32_t b0, uint32_t b1) {
    asm volatile(
        "mma.sync.aligned.m16n8k16.row.col.f32.bf16.bf16.f32 "
        "{%0,%1,%2,%3}, {%4,%5,%6,%7}, {%8,%9}, {%0,%1,%2,%3};"
        : "+f"(c[0]), "+f"(c[1]), "+f"(c[2]), "+f"(c[3])
        : "r"(a[0]), "r"(a[1]), "r"(a[2]), "r"(a[3]), "r"(b0), "r"(b1));
}

__device__ __forceinline__ void ldsm_x4(uint32_t* r, uint32_t addr) {
    asm volatile(
        "ldmatrix.sync.aligned.m8n8.x4.shared.b16 {%0,%1,%2,%3}, [%4];"
        : "=r"(r[0]), "=r"(r[1]), "=r"(r[2]), "=r"(r[3]) : "r"(addr));
}

__device__ __forceinline__ uint32_t smem_u32(const void* p) {
    uint32_t a;
    asm("{ .reg .u64 t; cvta.to.shared.u64 t, %1; cvt.u32.u64 %0, t; }"
        : "=r"(a) : "l"(p));
    return a;
}
__device__ __forceinline__ void cp16(uint32_t dst, const void* src) {
    asm volatile("cp.async.ca.shared.global [%0], [%1], 16;"
                 :: "r"(dst), "l"(src));
}
#define CP_COMMIT() asm volatile("cp.async.commit_group;" ::: "memory")
#define CP_WAIT1()  asm volatile("cp.async.wait_group 1;" ::: "memory")
#define CP_WAIT0()  asm volatile("cp.async.wait_group 0;" ::: "memory")

// FMA-pipe exp2 (input in log2 units). ~2e-6 rel err.
__device__ __forceinline__ float exp2p(float x) {
    x = fmaxf(x, -80.f);
    float t = x + 12582912.f;
    int n = __float_as_int(t) - 0x4B400000;
    float r = x - (t - 12582912.f);
    float p = 1.33335581e-3f;
    p = fmaf(p, r, 9.61812911e-3f);
    p = fmaf(p, r, 5.55041087e-2f);
    p = fmaf(p, r, 2.40226507e-1f);
    p = fmaf(p, r, 6.93147180e-1f);
    p = fmaf(p, r, 1.0f);
    return p * __int_as_float((n + 127) << 23);
}

constexpr float QSCALE = 0.125f * 1.44269504088896340736f;

// ---------------------------------------------------------------------------
// split: fp32 -> bf16 hi + lo
// ---------------------------------------------------------------------------
__global__ void split_kernel(const float* __restrict__ src,
                             __nv_bfloat16* __restrict__ hi,
                             __nv_bfloat16* __restrict__ lo, int n4) {
    int i = blockIdx.x * blockDim.x + threadIdx.x;
    if (i >= n4) return;
    float4 v = ((const float4*)src)[i];
    ((uint2*)hi)[i] = make_uint2(pack_bf16x2(v.x, v.y), pack_bf16x2(v.z, v.w));
    ((uint2*)lo)[i] = make_uint2(
        pack_bf16x2(bf16_resid(v.x), bf16_resid(v.y)),
        pack_bf16x2(bf16_resid(v.z), bf16_resid(v.w)));
}

// ---------------------------------------------------------------------------
// GEMM (R6 winner config): C = (Ah+Al) @ (Bh+Bl)^T + bias
// 128x128x32 tiles, 8 warps, 2-stage cp.async pipeline (2 CTAs/SM),
// ldmatrix fragments, split-major MMA issue order.
// ---------------------------------------------------------------------------
constexpr int GBK = 32;
constexpr int GSTR = 40;
constexpr int GTILE_E = 128 * GSTR;
constexpr int GSTAGE_E = 4 * GTILE_E;
constexpr int GSMEM = 2 * GSTAGE_E * 2;      // 81920 B -> 2 CTAs/SM

template <int MODE>
__global__ __launch_bounds__(256, 2) void gemm_cp(
    const __nv_bfloat16* __restrict__ Ah, const __nv_bfloat16* __restrict__ Al,
    const __nv_bfloat16* __restrict__ Bh, const __nv_bfloat16* __restrict__ Bl,
    const float* __restrict__ bias, float* __restrict__ C,
    int M, int N, int K)
{
    extern __shared__ __nv_bfloat16 smb[];
    const uint32_t smb_u = smem_u32(smb);
    const int tid = threadIdx.x;
    const int lane = tid & 31;
    const int w = tid >> 5;
    const int wm = w & 1, wn = w >> 1;
    const int g = lane >> 2, t = lane & 3;
    const int m0 = blockIdx.y * 128;
    const int n0 = blockIdx.x * 128;

    const __nv_bfloat16* bases[4] = {
        Ah + (size_t)m0 * K, Al + (size_t)m0 * K,
        Bh + (size_t)n0 * K, Bl + (size_t)n0 * K };

    const int nsteps = K / GBK;

    auto issue = [&](int s) {
        __nv_bfloat16* st = smb + (s & 1) * GSTAGE_E;
        const int k0 = s * GBK;
#pragma unroll
        for (int c = 0; c < 8; c++) {
            int ci = tid + c * 256;
            int arr = ci >> 9;
            int idx = ci & 511;
            int r = idx >> 2, ch = idx & 3;
            cp16(smem_u32(st + arr * GTILE_E + r * GSTR + ch * 8),
                 bases[arr] + (size_t)r * K + k0 + ch * 8);
        }
        CP_COMMIT();
    };

    const uint32_t a_off =
        (uint32_t)((wm * 64 + (lane & 15)) * GSTR + (lane >> 4) * 8) * 2;
    const uint32_t b_off =
        (uint32_t)((wn * 32 + ((lane >> 4) & 1) * 8 + (lane & 7)) * GSTR +
                   ((lane >> 3) & 1) * 8) * 2;

    float acc[4][4][4];
#pragma unroll
    for (int i = 0; i < 4; i++)
#pragma unroll
        for (int j = 0; j < 4; j++)
#pragma unroll
            for (int e = 0; e < 4; e++) acc[i][j][e] = 0.f;

    issue(0);
    issue(1);

    for (int s = 0; s < nsteps; s++) {
        if (s + 1 < nsteps) { CP_WAIT1(); } else { CP_WAIT0(); }
        __syncthreads();

        const uint32_t st = smb_u + (uint32_t)((s & 1) * GSTAGE_E) * 2;
        const uint32_t uAh = st;
        const uint32_t uAl = st + GTILE_E * 2;
        const uint32_t uBh = st + 2 * GTILE_E * 2;
        const uint32_t uBl = st + 3 * GTILE_E * 2;

#pragma unroll
        for (int ks = 0; ks < 2; ks++) {
            const uint32_t kso = (uint32_t)(ks * 16) * 2;
            uint32_t ah[4][4], al[4][4];
#pragma unroll
            for (int mt = 0; mt < 4; mt++) {
                const uint32_t ro = (uint32_t)(mt * 16 * GSTR) * 2;
                ldsm_x4(ah[mt], uAh + a_off + ro + kso);
                ldsm_x4(al[mt], uAl + a_off + ro + kso);
            }
#pragma unroll
            for (int p = 0; p < 2; p++) {
                const uint32_t ro = (uint32_t)(p * 16 * GSTR) * 2;
                uint32_t bh[4], bl[4];
                ldsm_x4(bh, uBh + b_off + ro + kso);
                ldsm_x4(bl, uBl + b_off + ro + kso);
#pragma unroll
                for (int mt = 0; mt < 4; mt++)
                    mma16816(acc[mt][2 * p], ah[mt], bh[0], bh[1]);
#pragma unroll
                for (int mt = 0; mt < 4; mt++)
                    mma16816(acc[mt][2 * p + 1], ah[mt], bh[2], bh[3]);
#pragma unroll
                for (int mt = 0; mt < 4; mt++)
                    mma16816(acc[mt][2 * p], al[mt], bh[0], bh[1]);
#pragma unroll
                for (int mt = 0; mt < 4; mt++)
                    mma16816(acc[mt][2 * p + 1], al[mt], bh[2], bh[3]);
#pragma unroll
                for (int mt = 0; mt < 4; mt++)
                    mma16816(acc[mt][2 * p], ah[mt], bl[0], bl[1]);
#pragma unroll
                for (int mt = 0; mt < 4; mt++)
                    mma16816(acc[mt][2 * p + 1], ah[mt], bl[2], bl[3]);
            }
        }

        __syncthreads();
        if (s + 2 < nsteps) issue(s + 2);
    }

    // ---- epilogue --------------------------------------------------------
#pragma unroll
    for (int mt = 0; mt < 4; mt++) {
#pragma unroll
        for (int nt = 0; nt < 4; nt++) {
            const int m = m0 + wm * 64 + mt * 16 + g;
            const int n = n0 + wn * 32 + nt * 8 + t * 2;
            const float* c = acc[mt][nt];
            float2 bv = *(const float2*)(bias + n);
            if (MODE == 0) {
                *(float2*)(C + (size_t)m * N + n) =
                    make_float2(c[0] + bv.x, c[1] + bv.y);
                *(float2*)(C + (size_t)(m + 8) * N + n) =
                    make_float2(c[2] + bv.x, c[3] + bv.y);
            } else {
                const int which = n >> 10;
                const int h = (n >> 6) & 15;
                const int d = n & 63;
                const float sc = (which == 1) ? QSCALE : 1.0f;
                __nv_bfloat16* dh = (which == 0 ? g_kh : which == 1 ? g_qh : g_vh);
                __nv_bfloat16* dl = (which == 0 ? g_kl : which == 1 ? g_ql : g_vl);
#pragma unroll
                for (int rr = 0; rr < 2; rr++) {
                    const int mm = m + rr * 8;
                    const int b = mm >> 11, s = mm & 2047;
                    const size_t off =
                        ((((size_t)b * H_ + h) * S_) + s) * D_ + d;
                    float v0 = (c[rr * 2 + 0] + bv.x) * sc;
                    float v1 = (c[rr * 2 + 1] + bv.y) * sc;
                    *(uint32_t*)(dh + off) = pack_bf16x2(v0, v1);
                    *(uint32_t*)(dl + off) =
                        pack_bf16x2(bf16_resid(v0), bf16_resid(v1));
                }
            }
        }
    }
}

// ---------------------------------------------------------------------------
// V transpose: [bh][s][d] -> [bh][d][s], hi and lo
// ---------------------------------------------------------------------------
__global__ __launch_bounds__(256) void vtrans_kernel() {
    __shared__ __nv_bfloat16 tile[64][72];
    const int tid = threadIdx.x;
    const int st = blockIdx.x;
    const int bh = blockIdx.y;

    const __nv_bfloat16* srcs[2] = {
        g_vh + ((size_t)bh * S_ + st * 64) * D_,
        g_vl + ((size_t)bh * S_ + st * 64) * D_ };
    __nv_bfloat16* dsts[2] = {
        g_vth + (size_t)bh * D_ * S_ + st * 64,
        g_vtl + (size_t)bh * D_ * S_ + st * 64 };

    for (int a = 0; a < 2; a++) {
        __syncthreads();
#pragma unroll
        for (int c = 0; c < 8; c++) {
            int ci = tid + c * 256;
            int r = ci >> 5, ch = ci & 31;
            *(uint32_t*)&tile[r][ch * 2] =
                *(const uint32_t*)(srcs[a] + (size_t)r * D_ + ch * 2);
        }
        __syncthreads();
#pragma unroll
        for (int c = 0; c < 8; c++) {
            int ci = tid + c * 256;
            int d = ci >> 5, s2 = (ci & 31) * 2;
            uint32_t o = (uint32_t)__bfloat16_as_ushort(tile[s2][d]) |
                         ((uint32_t)__bfloat16_as_ushort(tile[s2 + 1][d]) << 16);
            *(uint32_t*)(dsts[a] + (size_t)d * S_ + s2) = o;
        }
    }
}

// ---------------------------------------------------------------------------
// Tensor-core causal flash attention. CTA = (q-tile 128, bh), 8 warps.
// 2-stage KV ring -> 2 CTAs/SM; ldmatrix fragments (pair-hoisted);
// split-major MMA order; FMA-pipe exp2; fully-masked-warp skip.
// ---------------------------------------------------------------------------
constexpr int ASTR = 72;
constexpr int AQ_E = 2 * 128 * ASTR;
constexpr int AKT_E = 64 * ASTR;
constexpr int AKSTAGE_E = 4 * AKT_E;
constexpr int ASMEM = (AQ_E + 2 * AKSTAGE_E) * 2;   // 110592 B -> 2 CTAs/SM

__global__ __launch_bounds__(256, 2) void attn_mma() {
    extern __shared__ __nv_bfloat16 sma[];
    const uint32_t sma_u = smem_u32(sma);
    const int tid = threadIdx.x;
    const int lane = tid & 31;
    const int w = tid >> 5;
    const int g = lane >> 2, t = lane & 3;
    const int qt = (S_ / 128 - 1) - blockIdx.x;
    const int bh = blockIdx.y;
    const int nkt = 2 * qt + 2;

    __nv_bfloat16* QH = sma;
    __nv_bfloat16* QL = sma + 128 * ASTR;
    const uint32_t KV0_u = sma_u + AQ_E * 2;

    // ---- stage Q
    {
        const __nv_bfloat16* qsrc[2] = {
            g_qh + ((size_t)bh * S_ + qt * 128) * D_,
            g_ql + ((size_t)bh * S_ + qt * 128) * D_ };
#pragma unroll
        for (int c = 0; c < 8; c++) {
            int ci = tid + c * 256;
            int arr = ci >> 10;
            int idx = ci & 1023;
            int r = idx >> 3, ch = idx & 7;
            cp16(smem_u32(sma + arr * (128 * ASTR) + r * ASTR + ch * 8),
                 qsrc[arr] + (size_t)r * D_ + ch * 8);
        }
        CP_COMMIT();
    }

    auto issueKV = [&](int kt) {
        uint32_t st = KV0_u + (uint32_t)((kt & 1) * AKSTAGE_E) * 2;
        const __nv_bfloat16* bases[4] = {
            g_kh + ((size_t)bh * S_ + kt * 64) * D_,
            g_kl + ((size_t)bh * S_ + kt * 64) * D_,
            g_vth + (size_t)bh * D_ * S_ + kt * 64,
            g_vtl + (size_t)bh * D_ * S_ + kt * 64 };
#pragma unroll
        for (int c = 0; c < 8; c++) {
            int ci = tid + c * 256;
            int arr = ci >> 9;
            int idx = ci & 511;
            int r = idx >> 3, ch = idx & 7;
            const size_t rs = (arr < 2) ? (size_t)D_ : (size_t)S_;
            cp16(st + (uint32_t)(arr * AKT_E + r * ASTR + ch * 8) * 2,
                 bases[arr] + (size_t)r * rs + ch * 8);
        }
        CP_COMMIT();
    };

    issueKV(0);
    CP_WAIT1();            // Q complete (KV0 may still be in flight)
    __syncthreads();

    // ---- Q fragments (registers, whole CTA lifetime)
    uint32_t qfh[4][4], qfl[4][4];
#pragma unroll
    for (int ks = 0; ks < 4; ks++) {
        const int kb = ks * 16 + t * 2;
        const int r0 = (w * 16 + g) * ASTR;
        qfh[ks][0] = *(const uint32_t*)(QH + r0 + kb);
        qfh[ks][1] = *(const uint32_t*)(QH + r0 + 8 * ASTR + kb);
        qfh[ks][2] = *(const uint32_t*)(QH + r0 + kb + 8);
        qfh[ks][3] = *(const uint32_t*)(QH + r0 + 8 * ASTR + kb + 8);
        qfl[ks][0] = *(const uint32_t*)(QL + r0 + kb);
        qfl[ks][1] = *(const uint32_t*)(QL + r0 + 8 * ASTR + kb);
        qfl[ks][2] = *(const uint32_t*)(QL + r0 + kb + 8);
        qfl[ks][3] = *(const uint32_t*)(QL + r0 + 8 * ASTR + kb + 8);
    }

    const uint32_t bfrag_off =
        (uint32_t)((((lane >> 4) & 1) * 8 + (lane & 7)) * ASTR +
                   ((lane >> 3) & 1) * 8) * 2;

    float o[8][4];
#pragma unroll
    for (int nt = 0; nt < 8; nt++)
#pragma unroll
        for (int e = 0; e < 4; e++) o[nt][e] = 0.f;
    float m0 = -1e30f, m1 = -1e30f, l0 = 0.f, l1 = 0.f;

    const int row0 = qt * 128 + w * 16 + g;
    const int row1 = row0 + 8;

    for (int kt = 0; kt < nkt; kt++) {
        CP_WAIT0();
        __syncthreads();
        if (kt + 1 < nkt) issueKV(kt + 1);

        // fully-masked warp on the final (diagonal) k-tile: skip all MMAs
        if (kt * 64 > qt * 128 + w * 16 + 15) continue;

        const uint32_t st = KV0_u + (uint32_t)((kt & 1) * AKSTAGE_E) * 2;
        const uint32_t uKH = st;
        const uint32_t uKL = st + AKT_E * 2;
        const uint32_t uVH = st + 2 * AKT_E * 2;
        const uint32_t uVL = st + 3 * AKT_E * 2;

        // ---- S = Q @ K^T (pair-hoisted loads, split-major order)
        float sc[8][4];
#pragma unroll
        for (int nt = 0; nt < 8; nt++)
#pragma unroll
            for (int e = 0; e < 4; e++) sc[nt][e] = 0.f;

#pragma unroll
        for (int ks = 0; ks < 4; ks++) {
            const uint32_t kso = (uint32_t)(ks * 16) * 2;
#pragma unroll
            for (int np = 0; np < 2; np++) {           // pairs of ntp
                uint32_t kh4[2][4], kl4[2][4];
#pragma unroll
                for (int q2 = 0; q2 < 2; q2++) {
                    const uint32_t ro =
                        (uint32_t)(((np * 2 + q2) * 16) * ASTR) * 2;
                    ldsm_x4(kh4[q2], uKH + bfrag_off + ro + kso);
                    ldsm_x4(kl4[q2], uKL + bfrag_off + ro + kso);
                }
#pragma unroll
                for (int q2 = 0; q2 < 2; q2++) {
                    const int nt = (np * 2 + q2) * 2;
                    mma16816(sc[nt],     qfh[ks], kh4[q2][0], kh4[q2][1]);
                    mma16816(sc[nt + 1], qfh[ks], kh4[q2][2], kh4[q2][3]);
                }
#pragma unroll
                for (int q2 = 0; q2 < 2; q2++) {
                    const int nt = (np * 2 + q2) * 2;
                    mma16816(sc[nt],     qfl[ks], kh4[q2][0], kh4[q2][1]);
                    mma16816(sc[nt + 1], qfl[ks], kh4[q2][2], kh4[q2][3]);
                }
#pragma unroll
                for (int q2 = 0; q2 < 2; q2++) {
                    const int nt = (np * 2 + q2) * 2;
                    mma16816(sc[nt],     qfh[ks], kl4[q2][0], kl4[q2][1]);
                    mma16816(sc[nt + 1], qfh[ks], kl4[q2][2], kl4[q2][3]);
                }
            }
        }

        // ---- causal mask
        if (kt >= 2 * qt) {
#pragma unroll
            for (int nt = 0; nt < 8; nt++) {
                const int c0 = kt * 64 + nt * 8 + 2 * t;
                if (c0 > row0)     sc[nt][0] = -1e30f;
                if (c0 + 1 > row0) sc[nt][1] = -1e30f;
                if (c0 > row1)     sc[nt][2] = -1e30f;
                if (c0 + 1 > row1) sc[nt][3] = -1e30f;
            }
        }

        // ---- online softmax (base-2, FMA pipe)
        float mx0 = -1e30f, mx1 = -1e30f;
#pragma unroll
        for (int nt = 0; nt < 8; nt++) {
            mx0 = fmaxf(mx0, fmaxf(sc[nt][0], sc[nt][1]));
            mx1 = fmaxf(mx1, fmaxf(sc[nt][2], sc[nt][3]));
        }
        mx0 = fmaxf(mx0, __shfl_xor_sync(0xffffffffu, mx0, 1));
        mx0 = fmaxf(mx0, __shfl_xor_sync(0xffffffffu, mx0, 2));
        mx1 = fmaxf(mx1, __shfl_xor_sync(0xffffffffu, mx1, 1));
        mx1 = fmaxf(mx1, __shfl_xor_sync(0xffffffffu, mx1, 2));

        const float mn0 = fmaxf(m0, mx0), mn1 = fmaxf(m1, mx1);
        const float a0 = exp2p(m0 - mn0), a1 = exp2p(m1 - mn1);
        m0 = mn0; m1 = mn1;

        float rs0 = 0.f, rs1 = 0.f;
#pragma unroll
        for (int nt = 0; nt < 8; nt++) {
            sc[nt][0] = exp2p(sc[nt][0] - mn0);
            sc[nt][1] = exp2p(sc[nt][1] - mn0);
            sc[nt][2] = exp2p(sc[nt][2] - mn1);
            sc[nt][3] = exp2p(sc[nt][3] - mn1);
            rs0 += sc[nt][0] + sc[nt][1];
            rs1 += sc[nt][2] + sc[nt][3];
        }
        rs0 += __shfl_xor_sync(0xffffffffu, rs0, 1);
        rs0 += __shfl_xor_sync(0xffffffffu, rs0, 2);
        rs1 += __shfl_xor_sync(0xffffffffu, rs1, 1);
        rs1 += __shfl_xor_sync(0xffffffffu, rs1, 2);
        l0 = l0 * a0 + rs0;
        l1 = l1 * a1 + rs1;

#pragma unroll
        for (int nt = 0; nt < 8; nt++) {
            o[nt][0] *= a0; o[nt][1] *= a0;
            o[nt][2] *= a1; o[nt][3] *= a1;
        }

        // ---- P fragments (FA layout) + hi/lo split
        uint32_t pfh[4][4], pfl[4][4];
#pragma unroll
        for (int ks = 0; ks < 4; ks++) {
            const float* p0 = sc[2 * ks];
            const float* p1 = sc[2 * ks + 1];
            pfh[ks][0] = pack_bf16x2(p0[0], p0[1]);
            pfh[ks][1] = pack_bf16x2(p0[2], p0[3]);
            pfh[ks][2] = pack_bf16x2(p1[0], p1[1]);
            pfh[ks][3] = pack_bf16x2(p1[2], p1[3]);
            pfl[ks][0] = pack_bf16x2(bf16_resid(p0[0]), bf16_resid(p0[1]));
            pfl[ks][1] = pack_bf16x2(bf16_resid(p0[2]), bf16_resid(p0[3]));
            pfl[ks][2] = pack_bf16x2(bf16_resid(p1[0]), bf16_resid(p1[1]));
            pfl[ks][3] = pack_bf16x2(bf16_resid(p1[2]), bf16_resid(p1[3]));
        }

        // ---- O += P @ V (pair-hoisted loads, split-major order)
#pragma unroll
        for (int ks = 0; ks < 4; ks++) {
            const uint32_t kso = (uint32_t)(ks * 16) * 2;
#pragma unroll
            for (int np = 0; np < 2; np++) {
                uint32_t vh4[2][4], vl4[2][4];
#pragma unroll
                for (int q2 = 0; q2 < 2; q2++) {
                    const uint32_t ro =
                        (uint32_t)(((np * 2 + q2) * 16) * ASTR) * 2;
                    ldsm_x4(vh4[q2], uVH + bfrag_off + ro + kso);
                    ldsm_x4(vl4[q2], uVL + bfrag_off + ro + kso);
                }
#pragma unroll
                for (int q2 = 0; q2 < 2; q2++) {
                    const int nt = (np * 2 + q2) * 2;
                    mma16816(o[nt],     pfh[ks], vh4[q2][0], vh4[q2][1]);
                    mma16816(o[nt + 1], pfh[ks], vh4[q2][2], vh4[q2][3]);
                }
#pragma unroll
                for (int q2 = 0; q2 < 2; q2++) {
                    const int nt = (np * 2 + q2) * 2;
                    mma16816(o[nt],     pfl[ks], vh4[q2][0], vh4[q2][1]);
                    mma16816(o[nt + 1], pfl[ks], vh4[q2][2], vh4[q2][3]);
                }
#pragma unroll
                for (int q2 = 0; q2 < 2; q2++) {
                    const int nt = (np * 2 + q2) * 2;
                    mma16816(o[nt],     pfh[ks], vl4[q2][0], vl4[q2][1]);
                    mma16816(o[nt + 1], pfh[ks], vl4[q2][2], vl4[q2][3]);
                }
            }
        }
    }

    // ---- epilogue: y = O / l, bf16 hi/lo, [b][s][h*64+d]
    const float inv0 = 1.0f / l0, inv1 = 1.0f / l1;
    const int b = bh >> 4, h = bh & 15;
#pragma unroll
    for (int nt = 0; nt < 8; nt++) {
        const int e = h * 64 + nt * 8 + 2 * t;
        {
            const size_t off = ((size_t)b * S_ + row0) * E_ + e;
            float v0 = o[nt][0] * inv0, v1 = o[nt][1] * inv0;
            *(uint32_t*)(g_yh + off) = pack_bf16x2(v0, v1);
            *(uint32_t*)(g_yl + off) =
                pack_bf16x2(bf16_resid(v0), bf16_resid(v1));
        }
        {
            const size_t off = ((size_t)b * S_ + row1) * E_ + e;
            float v0 = o[nt][2] * inv1, v1 = o[nt][3] * inv1;
            *(uint32_t*)(g_yh + off) = pack_bf16x2(v0, v1);
            *(uint32_t*)(g_yl + off) =
                pack_bf16x2(bf16_resid(v0), bf16_resid(v1));
        }
    }
}

// ---------------------------------------------------------------------------
// Launch
// ---------------------------------------------------------------------------
extern "C" void kernel_launch(void* const* d_in, const int* in_sizes, int n_in,
                              void* d_out, int out_size)
{
    const float* x      = (const float*)d_in[0];
    const float* W_kqv  = (const float*)d_in[1];
    const float* b_kqv  = (const float*)d_in[2];
    const float* W_proj = (const float*)d_in[3];
    const float* b_proj = (const float*)d_in[4];
    float* out = (float*)d_out;

    void *xh, *xl, *wkh, *wkl, *wph, *wpl, *yh, *yl;
    cudaGetSymbolAddress(&xh, g_xh);   cudaGetSymbolAddress(&xl, g_xl);
    cudaGetSymbolAddress(&wkh, g_wkh); cudaGetSymbolAddress(&wkl, g_wkl);
    cudaGetSymbolAddress(&wph, g_wph); cudaGetSymbolAddress(&wpl, g_wpl);
    cudaGetSymbolAddress(&yh, g_yh);   cudaGetSymbolAddress(&yl, g_yl);

    cudaFuncSetAttribute(gemm_cp<0>, cudaFuncAttributeMaxDynamicSharedMemorySize, GSMEM);
    cudaFuncSetAttribute(gemm_cp<1>, cudaFuncAttributeMaxDynamicSharedMemorySize, GSMEM);
    cudaFuncSetAttribute(attn_mma,   cudaFuncAttributeMaxDynamicSharedMemorySize, ASMEM);

    // 0) split inputs to bf16 hi/lo
    {
        int n4 = M_ * E_ / 4;
        split_kernel<<<(n4 + 255) / 256, 256>>>(
            x, (__nv_bfloat16*)xh, (__nv_bfloat16*)xl, n4);
        n4 = NKQV * E_ / 4;
        split_kernel<<<(n4 + 255) / 256, 256>>>(
            W_kqv, (__nv_bfloat16*)wkh, (__nv_bfloat16*)wkl, n4);
        n4 = E_ * E_ / 4;
        split_kernel<<<(n4 + 255) / 256, 256>>>(
            W_proj, (__nv_bfloat16*)wph, (__nv_bfloat16*)wpl, n4);
    }

    // 1) QKV projection -> q/k/v bf16 hi/lo (q pre-scaled)
    gemm_cp<1><<<dim3(NKQV / 128, M_ / 128), 256, GSMEM>>>(
        (const __nv_bfloat16*)xh, (const __nv_bfloat16*)xl,
        (const __nv_bfloat16*)wkh, (const __nv_bfloat16*)wkl,
        b_kqv, nullptr, M_, NKQV, E_);

    // 2) V transpose [bh][s][d] -> [bh][d][s]
    vtrans_kernel<<<dim3(S_ / 64, B_ * H_), 256>>>();

    // 3) Tensor-core causal flash attention -> y bf16 hi/lo
    attn_mma<<<dim3(S_ / 128, B_ * H_), 256, ASMEM>>>();

    // 4) Output projection -> d_out (fp32)
    gemm_cp<0><<<dim3(E_ / 128, M_ / 128), 256, GSMEM>>>(
        (const __nv_bfloat16*)yh, (const __nv_bfloat16*)yl,
        (const __nv_bfloat16*)wph, (const __nv_bfloat16*)wpl,
        b_proj, out, M_, E_, E_);
}

// round 9
// speedup vs baseline: 1.1347x; 1.1045x over previous
#include <cuda_runtime.h>
#include <cuda_bf16.h>
#include <cuda_fp16.h>
#include <cstdint>
#include <math.h>

// Problem constants
constexpr int B_ = 4, S_ = 2048, E_ = 1024, H_ = 16, D_ = 64;
constexpr int M_ = B_ * S_;            // 8192 rows
constexpr int NKQV = 3 * E_;           // 3072

// ---------------------------------------------------------------------------
// Scratch (device globals)
// ---------------------------------------------------------------------------
__device__ __nv_bfloat16 g_xh[(size_t)M_ * E_],  g_xl[(size_t)M_ * E_];
__device__ __nv_bfloat16 g_wkh[(size_t)NKQV * E_], g_wkl[(size_t)NKQV * E_];
__device__ __half        g_wph[(size_t)E_ * E_], g_wpl[(size_t)E_ * E_];
__device__ __nv_bfloat16 g_qh[(size_t)B_*H_*S_*D_], g_ql[(size_t)B_*H_*S_*D_];
__device__ __nv_bfloat16 g_kh[(size_t)B_*H_*S_*D_], g_kl[(size_t)B_*H_*S_*D_];
__device__ __nv_bfloat16 g_vh[(size_t)B_*H_*S_*D_], g_vl[(size_t)B_*H_*S_*D_];
__device__ __nv_bfloat16 g_vth[(size_t)B_*H_*S_*D_], g_vtl[(size_t)B_*H_*S_*D_];
__device__ __half        g_yh[(size_t)M_ * E_];

// ---------------------------------------------------------------------------
// helpers
// ---------------------------------------------------------------------------
__device__ __forceinline__ uint32_t pack_bf16x2(float a, float b) {
    __nv_bfloat16 ha = __float2bfloat16_rn(a);
    __nv_bfloat16 hb = __float2bfloat16_rn(b);
    return (uint32_t)__bfloat16_as_ushort(ha) |
           ((uint32_t)__bfloat16_as_ushort(hb) << 16);
}
__device__ __forceinline__ float bf16_resid(float a) {
    return a - __bfloat162float(__float2bfloat16_rn(a));
}
__device__ __forceinline__ uint32_t pack_f16x2(float a, float b) {
    __half2 h = __floats2half2_rn(a, b);
    return *(uint32_t*)&h;
}

__device__ __forceinline__ void mma16816(float* c, const uint32_t* a,
                                         uint32_t b0, uint32_t b1) {
    asm volatile(
        "mma.sync.aligned.m16n8k16.row.col.f32.bf16.bf16.f32 "
        "{%0,%1,%2,%3}, {%4,%5,%6,%7}, {%8,%9}, {%0,%1,%2,%3};"
        : "+f"(c[0]), "+f"(c[1]), "+f"(c[2]), "+f"(c[3])
        : "r"(a[0]), "r"(a[1]), "r"(a[2]), "r"(a[3]), "r"(b0), "r"(b1));
}
__device__ __forceinline__ void mma16816h(float* c, const uint32_t* a,
                                          uint32_t b0, uint32_t b1) {
    asm volatile(
        "mma.sync.aligned.m16n8k16.row.col.f32.f16.f16.f32 "
        "{%0,%1,%2,%3}, {%4,%5,%6,%7}, {%8,%9}, {%0,%1,%2,%3};"
        : "+f"(c[0]), "+f"(c[1]), "+f"(c[2]), "+f"(c[3])
        : "r"(a[0]), "r"(a[1]), "r"(a[2]), "r"(a[3]), "r"(b0), "r"(b1));
}

__device__ __forceinline__ void ldsm_x4(uint32_t* r, uint32_t addr) {
    asm volatile(
        "ldmatrix.sync.aligned.m8n8.x4.shared.b16 {%0,%1,%2,%3}, [%4];"
        : "=r"(r[0]), "=r"(r[1]), "=r"(r[2]), "=r"(r[3]) : "r"(addr));
}

__device__ __forceinline__ uint32_t smem_u32(const void* p) {
    uint32_t a;
    asm("{ .reg .u64 t; cvta.to.shared.u64 t, %1; cvt.u32.u64 %0, t; }"
        : "=r"(a) : "l"(p));
    return a;
}
__device__ __forceinline__ void cp16(uint32_t dst, const void* src) {
    asm volatile("cp.async.ca.shared.global [%0], [%1], 16;"
                 :: "r"(dst), "l"(src));
}
#define CP_COMMIT() asm volatile("cp.async.commit_group;" ::: "memory")
#define CP_WAIT1()  asm volatile("cp.async.wait_group 1;" ::: "memory")
#define CP_WAIT0()  asm volatile("cp.async.wait_group 0;" ::: "memory")

// FMA-pipe exp2 (input in log2 units). ~2e-6 rel err.
__device__ __forceinline__ float exp2p(float x) {
    x = fmaxf(x, -80.f);
    float t = x + 12582912.f;
    int n = __float_as_int(t) - 0x4B400000;
    float r = x - (t - 12582912.f);
    float p = 1.33335581e-3f;
    p = fmaf(p, r, 9.61812911e-3f);
    p = fmaf(p, r, 5.55041087e-2f);
    p = fmaf(p, r, 2.40226507e-1f);
    p = fmaf(p, r, 6.93147180e-1f);
    p = fmaf(p, r, 1.0f);
    return p * __int_as_float((n + 127) << 23);
}

constexpr float QSCALE = 0.125f * 1.44269504088896340736f;

// ---------------------------------------------------------------------------
// splits
// ---------------------------------------------------------------------------
__global__ void split_kernel(const float* __restrict__ src,
                             __nv_bfloat16* __restrict__ hi,
                             __nv_bfloat16* __restrict__ lo, int n4) {
    int i = blockIdx.x * blockDim.x + threadIdx.x;
    if (i >= n4) return;
    float4 v = ((const float4*)src)[i];
    ((uint2*)hi)[i] = make_uint2(pack_bf16x2(v.x, v.y), pack_bf16x2(v.z, v.w));
    ((uint2*)lo)[i] = make_uint2(
        pack_bf16x2(bf16_resid(v.x), bf16_resid(v.y)),
        pack_bf16x2(bf16_resid(v.z), bf16_resid(v.w)));
}

__global__ void splitH_kernel(const float* __restrict__ src,
                              __half* __restrict__ hi,
                              __half* __restrict__ lo, int n4) {
    int i = blockIdx.x * blockDim.x + threadIdx.x;
    if (i >= n4) return;
    float4 v = ((const float4*)src)[i];
    float hx = __half2float(__float2half_rn(v.x));
    float hy = __half2float(__float2half_rn(v.y));
    float hz = __half2float(__float2half_rn(v.z));
    float hw = __half2float(__float2half_rn(v.w));
    ((uint2*)hi)[i] = make_uint2(pack_f16x2(v.x, v.y), pack_f16x2(v.z, v.w));
    ((uint2*)lo)[i] = make_uint2(pack_f16x2(v.x - hx, v.y - hy),
                                 pack_f16x2(v.z - hz, v.w - hw));
}

// ---------------------------------------------------------------------------
// QKV GEMM: bf16 3-MMA split. 128x128x32 tiles, 4 warps of 64x64,
// 128 threads, 2-stage cp.async, 2 CTAs/SM.
// ---------------------------------------------------------------------------
constexpr int GBK = 32;
constexpr int GSTR = 40;
constexpr int GTILE_E = 128 * GSTR;          // 5120
constexpr int GSTAGE_E = 4 * GTILE_E;        // 20480
constexpr int GSMEM = 2 * GSTAGE_E * 2;      // 81920 B

__global__ __launch_bounds__(128, 2) void gemm_qkv(
    const __nv_bfloat16* __restrict__ Ah, const __nv_bfloat16* __restrict__ Al,
    const __nv_bfloat16* __restrict__ Bh, const __nv_bfloat16* __restrict__ Bl,
    const float* __restrict__ bias, int K)
{
    extern __shared__ __nv_bfloat16 smb[];
    const uint32_t smb_u = smem_u32(smb);
    const int tid = threadIdx.x;
    const int lane = tid & 31;
    const int w = tid >> 5;
    const int wm = w & 1, wn = w >> 1;
    const int g = lane >> 2, t = lane & 3;
    const int m0 = blockIdx.y * 128;
    const int n0 = blockIdx.x * 128;

    const __nv_bfloat16* bases[4] = {
        Ah + (size_t)m0 * K, Al + (size_t)m0 * K,
        Bh + (size_t)n0 * K, Bl + (size_t)n0 * K };

    const int nsteps = K / GBK;

    auto issue = [&](int s) {
        __nv_bfloat16* st = smb + (s & 1) * GSTAGE_E;
        const int k0 = s * GBK;
#pragma unroll
        for (int c = 0; c < 16; c++) {
            int ci = tid + c * 128;
            int arr = ci >> 9;
            int idx = ci & 511;
            int r = idx >> 2, ch = idx & 3;
            cp16(smem_u32(st + arr * GTILE_E + r * GSTR + ch * 8),
                 bases[arr] + (size_t)r * K + k0 + ch * 8);
        }
        CP_COMMIT();
    };

    const uint32_t a_off =
        (uint32_t)((wm * 64 + (lane & 15)) * GSTR + (lane >> 4) * 8) * 2;
    const uint32_t b_off =
        (uint32_t)((wn * 64 + ((lane >> 4) & 1) * 8 + (lane & 7)) * GSTR +
                   ((lane >> 3) & 1) * 8) * 2;

    float acc[4][8][4];
#pragma unroll
    for (int i = 0; i < 4; i++)
#pragma unroll
        for (int j = 0; j < 8; j++)
#pragma unroll
            for (int e = 0; e < 4; e++) acc[i][j][e] = 0.f;

    issue(0);
    issue(1);

    for (int s = 0; s < nsteps; s++) {
        if (s + 1 < nsteps) { CP_WAIT1(); } else { CP_WAIT0(); }
        __syncthreads();

        const uint32_t st = smb_u + (uint32_t)((s & 1) * GSTAGE_E) * 2;
        const uint32_t uAh = st;
        const uint32_t uAl = st + GTILE_E * 2;
        const uint32_t uBh = st + 2 * GTILE_E * 2;
        const uint32_t uBl = st + 3 * GTILE_E * 2;

#pragma unroll
        for (int ks = 0; ks < 2; ks++) {
            const uint32_t kso = (uint32_t)(ks * 16) * 2;
            uint32_t ah[4][4], al[4][4];
#pragma unroll
            for (int mt = 0; mt < 4; mt++) {
                const uint32_t ro = (uint32_t)(mt * 16 * GSTR) * 2;
                ldsm_x4(ah[mt], uAh + a_off + ro + kso);
                ldsm_x4(al[mt], uAl + a_off + ro + kso);
            }
#pragma unroll
            for (int pp = 0; pp < 2; pp++) {     // pairs of 16-col groups
                uint32_t bh[2][4], bl[2][4];
#pragma unroll
                for (int q2 = 0; q2 < 2; q2++) {
                    const uint32_t ro =
                        (uint32_t)(((pp * 2 + q2) * 16) * GSTR) * 2;
                    ldsm_x4(bh[q2], uBh + b_off + ro + kso);
                    ldsm_x4(bl[q2], uBl + b_off + ro + kso);
                }
                // split-major: hi*hi, lo*hi, hi*lo (reuse distance 8)
#pragma unroll
                for (int q2 = 0; q2 < 2; q2++) {
                    const int nt = (pp * 2 + q2) * 2;
#pragma unroll
                    for (int mt = 0; mt < 4; mt++) {
                        mma16816(acc[mt][nt],     ah[mt], bh[q2][0], bh[q2][1]);
                        mma16816(acc[mt][nt + 1], ah[mt], bh[q2][2], bh[q2][3]);
                    }
                }
#pragma unroll
                for (int q2 = 0; q2 < 2; q2++) {
                    const int nt = (pp * 2 + q2) * 2;
#pragma unroll
                    for (int mt = 0; mt < 4; mt++) {
                        mma16816(acc[mt][nt],     al[mt], bh[q2][0], bh[q2][1]);
                        mma16816(acc[mt][nt + 1], al[mt], bh[q2][2], bh[q2][3]);
                    }
                }
#pragma unroll
                for (int q2 = 0; q2 < 2; q2++) {
                    const int nt = (pp * 2 + q2) * 2;
#pragma unroll
                    for (int mt = 0; mt < 4; mt++) {
                        mma16816(acc[mt][nt],     ah[mt], bl[q2][0], bl[q2][1]);
                        mma16816(acc[mt][nt + 1], ah[mt], bl[q2][2], bl[q2][3]);
                    }
                }
            }
        }

        __syncthreads();
        if (s + 2 < nsteps) issue(s + 2);
    }

    // ---- epilogue: scatter into q/k/v bf16 hi/lo -------------------------
#pragma unroll
    for (int mt = 0; mt < 4; mt++) {
#pragma unroll
        for (int nt = 0; nt < 8; nt++) {
            const int m = m0 + wm * 64 + mt * 16 + g;
            const int n = n0 + wn * 64 + nt * 8 + t * 2;
            const float* c = acc[mt][nt];
            float2 bv = *(const float2*)(bias + n);
            const int which = n >> 10;
            const int h = (n >> 6) & 15;
            const int d = n & 63;
            const float sc = (which == 1) ? QSCALE : 1.0f;
            __nv_bfloat16* dh = (which == 0 ? g_kh : which == 1 ? g_qh : g_vh);
            __nv_bfloat16* dl = (which == 0 ? g_kl : which == 1 ? g_ql : g_vl);
#pragma unroll
            for (int rr = 0; rr < 2; rr++) {
                const int mm = m + rr * 8;
                const int b = mm >> 11, s = mm & 2047;
                const size_t off = ((((size_t)b * H_ + h) * S_) + s) * D_ + d;
                float v0 = (c[rr * 2 + 0] + bv.x) * sc;
                float v1 = (c[rr * 2 + 1] + bv.y) * sc;
                *(uint32_t*)(dh + off) = pack_bf16x2(v0, v1);
                *(uint32_t*)(dl + off) =
                    pack_bf16x2(bf16_resid(v0), bf16_resid(v1));
            }
        }
    }
}

// ---------------------------------------------------------------------------
// Proj GEMM: fp16 2-MMA scheme (A = y in fp16; B = W_proj fp16 hi+lo).
// 128x128x32 tiles, 4 warps of 64x64, 128 threads, 2-stage, 2 CTAs/SM.
// ---------------------------------------------------------------------------
constexpr int PSTAGE_E = 3 * GTILE_E;        // 15360 (Ah, Bh, Bl)
constexpr int PSMEM = 2 * PSTAGE_E * 2;      // 61440 B

__global__ __launch_bounds__(128, 2) void gemm_proj(
    const __half* __restrict__ Ah,
    const __half* __restrict__ Bh, const __half* __restrict__ Bl,
    const float* __restrict__ bias, float* __restrict__ C, int N, int K)
{
    extern __shared__ __half smh[];
    const uint32_t smb_u = smem_u32(smh);
    const int tid = threadIdx.x;
    const int lane = tid & 31;
    const int w = tid >> 5;
    const int wm = w & 1, wn = w >> 1;
    const int g = lane >> 2, t = lane & 3;
    const int m0 = blockIdx.y * 128;
    const int n0 = blockIdx.x * 128;

    const __half* bases[3] = {
        Ah + (size_t)m0 * K, Bh + (size_t)n0 * K, Bl + (size_t)n0 * K };

    const int nsteps = K / GBK;

    auto issue = [&](int s) {
        __half* st = smh + (s & 1) * PSTAGE_E;
        const int k0 = s * GBK;
#pragma unroll
        for (int c = 0; c < 12; c++) {
            int ci = tid + c * 128;
            int arr = ci >> 9;
            int idx = ci & 511;
            int r = idx >> 2, ch = idx & 3;
            cp16(smem_u32(st + arr * GTILE_E + r * GSTR + ch * 8),
                 bases[arr] + (size_t)r * K + k0 + ch * 8);
        }
        CP_COMMIT();
    };

    const uint32_t a_off =
        (uint32_t)((wm * 64 + (lane & 15)) * GSTR + (lane >> 4) * 8) * 2;
    const uint32_t b_off =
        (uint32_t)((wn * 64 + ((lane >> 4) & 1) * 8 + (lane & 7)) * GSTR +
                   ((lane >> 3) & 1) * 8) * 2;

    float acc[4][8][4];
#pragma unroll
    for (int i = 0; i < 4; i++)
#pragma unroll
        for (int j = 0; j < 8; j++)
#pragma unroll
            for (int e = 0; e < 4; e++) acc[i][j][e] = 0.f;

    issue(0);
    issue(1);

    for (int s = 0; s < nsteps; s++) {
        if (s + 1 < nsteps) { CP_WAIT1(); } else { CP_WAIT0(); }
        __syncthreads();

        const uint32_t st = smb_u + (uint32_t)((s & 1) * PSTAGE_E) * 2;
        const uint32_t uAh = st;
        const uint32_t uBh = st + GTILE_E * 2;
        const uint32_t uBl = st + 2 * GTILE_E * 2;

#pragma unroll
        for (int ks = 0; ks < 2; ks++) {
            const uint32_t kso = (uint32_t)(ks * 16) * 2;
            uint32_t ah[4][4];
#pragma unroll
            for (int mt = 0; mt < 4; mt++) {
                const uint32_t ro = (uint32_t)(mt * 16 * GSTR) * 2;
                ldsm_x4(ah[mt], uAh + a_off + ro + kso);
            }
#pragma unroll
            for (int pp = 0; pp < 2; pp++) {
                uint32_t bh[2][4], bl[2][4];
#pragma unroll
                for (int q2 = 0; q2 < 2; q2++) {
                    const uint32_t ro =
                        (uint32_t)(((pp * 2 + q2) * 16) * GSTR) * 2;
                    ldsm_x4(bh[q2], uBh + b_off + ro + kso);
                    ldsm_x4(bl[q2], uBl + b_off + ro + kso);
                }
#pragma unroll
                for (int q2 = 0; q2 < 2; q2++) {
                    const int nt = (pp * 2 + q2) * 2;
#pragma unroll
                    for (int mt = 0; mt < 4; mt++) {
                        mma16816h(acc[mt][nt],     ah[mt], bh[q2][0], bh[q2][1]);
                        mma16816h(acc[mt][nt + 1], ah[mt], bh[q2][2], bh[q2][3]);
                    }
                }
#pragma unroll
                for (int q2 = 0; q2 < 2; q2++) {
                    const int nt = (pp * 2 + q2) * 2;
#pragma unroll
                    for (int mt = 0; mt < 4; mt++) {
                        mma16816h(acc[mt][nt],     ah[mt], bl[q2][0], bl[q2][1]);
                        mma16816h(acc[mt][nt + 1], ah[mt], bl[q2][2], bl[q2][3]);
                    }
                }
            }
        }

        __syncthreads();
        if (s + 2 < nsteps) issue(s + 2);
    }

    // ---- epilogue: fp32 row-major ----------------------------------------
#pragma unroll
    for (int mt = 0; mt < 4; mt++) {
#pragma unroll
        for (int nt = 0; nt < 8; nt++) {
            const int m = m0 + wm * 64 + mt * 16 + g;
            const int n = n0 + wn * 64 + nt * 8 + t * 2;
            const float* c = acc[mt][nt];
            float2 bv = *(const float2*)(bias + n);
            *(float2*)(C + (size_t)m * N + n) =
                make_float2(c[0] + bv.x, c[1] + bv.y);
            *(float2*)(C + (size_t)(m + 8) * N + n) =
                make_float2(c[2] + bv.x, c[3] + bv.y);
        }
    }
}

// ---------------------------------------------------------------------------
// V transpose: [bh][s][d] -> [bh][d][s], hi and lo
// ---------------------------------------------------------------------------
__global__ __launch_bounds__(256) void vtrans_kernel() {
    __shared__ __nv_bfloat16 tile[64][72];
    const int tid = threadIdx.x;
    const int st = blockIdx.x;
    const int bh = blockIdx.y;

    const __nv_bfloat16* srcs[2] = {
        g_vh + ((size_t)bh * S_ + st * 64) * D_,
        g_vl + ((size_t)bh * S_ + st * 64) * D_ };
    __nv_bfloat16* dsts[2] = {
        g_vth + (size_t)bh * D_ * S_ + st * 64,
        g_vtl + (size_t)bh * D_ * S_ + st * 64 };

    for (int a = 0; a < 2; a++) {
        __syncthreads();
#pragma unroll
        for (int c = 0; c < 8; c++) {
            int ci = tid + c * 256;
            int r = ci >> 5, ch = ci & 31;
            *(uint32_t*)&tile[r][ch * 2] =
                *(const uint32_t*)(srcs[a] + (size_t)r * D_ + ch * 2);
        }
        __syncthreads();
#pragma unroll
        for (int c = 0; c < 8; c++) {
            int ci = tid + c * 256;
            int d = ci >> 5, s2 = (ci & 31) * 2;
            uint32_t o = (uint32_t)__bfloat16_as_ushort(tile[s2][d]) |
                         ((uint32_t)__bfloat16_as_ushort(tile[s2 + 1][d]) << 16);
            *(uint32_t*)(dsts[a] + (size_t)d * S_ + s2) = o;
        }
    }
}

// ---------------------------------------------------------------------------
// Tensor-core causal flash attention (R8 config; epilogue now fp16 y only).
// ---------------------------------------------------------------------------
constexpr int ASTR = 72;
constexpr int AQ_E = 2 * 128 * ASTR;
constexpr int AKT_E = 64 * ASTR;
constexpr int AKSTAGE_E = 4 * AKT_E;
constexpr int ASMEM = (AQ_E + 2 * AKSTAGE_E) * 2;   // 110592 B -> 2 CTAs/SM

__global__ __launch_bounds__(256, 2) void attn_mma() {
    extern __shared__ __nv_bfloat16 sma[];
    const uint32_t sma_u = smem_u32(sma);
    const int tid = threadIdx.x;
    const int lane = tid & 31;
    const int w = tid >> 5;
    const int g = lane >> 2, t = lane & 3;
    const int qt = (S_ / 128 - 1) - blockIdx.x;
    const int bh = blockIdx.y;
    const int nkt = 2 * qt + 2;

    __nv_bfloat16* QH = sma;
    __nv_bfloat16* QL = sma + 128 * ASTR;
    const uint32_t KV0_u = sma_u + AQ_E * 2;

    {
        const __nv_bfloat16* qsrc[2] = {
            g_qh + ((size_t)bh * S_ + qt * 128) * D_,
            g_ql + ((size_t)bh * S_ + qt * 128) * D_ };
#pragma unroll
        for (int c = 0; c < 8; c++) {
            int ci = tid + c * 256;
            int arr = ci >> 10;
            int idx = ci & 1023;
            int r = idx >> 3, ch = idx & 7;
            cp16(smem_u32(sma + arr * (128 * ASTR) + r * ASTR + ch * 8),
                 qsrc[arr] + (size_t)r * D_ + ch * 8);
        }
        CP_COMMIT();
    }

    auto issueKV = [&](int kt) {
        uint32_t st = KV0_u + (uint32_t)((kt & 1) * AKSTAGE_E) * 2;
        const __nv_bfloat16* bases[4] = {
            g_kh + ((size_t)bh * S_ + kt * 64) * D_,
            g_kl + ((size_t)bh * S_ + kt * 64) * D_,
            g_vth + (size_t)bh * D_ * S_ + kt * 64,
            g_vtl + (size_t)bh * D_ * S_ + kt * 64 };
#pragma unroll
        for (int c = 0; c < 8; c++) {
            int ci = tid + c * 256;
            int arr = ci >> 9;
            int idx = ci & 511;
            int r = idx >> 3, ch = idx & 7;
            const size_t rs = (arr < 2) ? (size_t)D_ : (size_t)S_;
            cp16(st + (uint32_t)(arr * AKT_E + r * ASTR + ch * 8) * 2,
                 bases[arr] + (size_t)r * rs + ch * 8);
        }
        CP_COMMIT();
    };

    issueKV(0);
    CP_WAIT1();
    __syncthreads();

    uint32_t qfh[4][4], qfl[4][4];
#pragma unroll
    for (int ks = 0; ks < 4; ks++) {
        const int kb = ks * 16 + t * 2;
        const int r0 = (w * 16 + g) * ASTR;
        qfh[ks][0] = *(const uint32_t*)(QH + r0 + kb);
        qfh[ks][1] = *(const uint32_t*)(QH + r0 + 8 * ASTR + kb);
        qfh[ks][2] = *(const uint32_t*)(QH + r0 + kb + 8);
        qfh[ks][3] = *(const uint32_t*)(QH + r0 + 8 * ASTR + kb + 8);
        qfl[ks][0] = *(const uint32_t*)(QL + r0 + kb);
        qfl[ks][1] = *(const uint32_t*)(QL + r0 + 8 * ASTR + kb);
        qfl[ks][2] = *(const uint32_t*)(QL + r0 + kb + 8);
        qfl[ks][3] = *(const uint32_t*)(QL + r0 + 8 * ASTR + kb + 8);
    }

    const uint32_t bfrag_off =
        (uint32_t)((((lane >> 4) & 1) * 8 + (lane & 7)) * ASTR +
                   ((lane >> 3) & 1) * 8) * 2;

    float o[8][4];
#pragma unroll
    for (int nt = 0; nt < 8; nt++)
#pragma unroll
        for (int e = 0; e < 4; e++) o[nt][e] = 0.f;
    float m0 = -1e30f, m1 = -1e30f, l0 = 0.f, l1 = 0.f;

    const int row0 = qt * 128 + w * 16 + g;
    const int row1 = row0 + 8;

    for (int kt = 0; kt < nkt; kt++) {
        CP_WAIT0();
        __syncthreads();
        if (kt + 1 < nkt) issueKV(kt + 1);

        if (kt * 64 > qt * 128 + w * 16 + 15) continue;

        const uint32_t st = KV0_u + (uint32_t)((kt & 1) * AKSTAGE_E) * 2;
        const uint32_t uKH = st;
        const uint32_t uKL = st + AKT_E * 2;
        const uint32_t uVH = st + 2 * AKT_E * 2;
        const uint32_t uVL = st + 3 * AKT_E * 2;

        float sc[8][4];
#pragma unroll
        for (int nt = 0; nt < 8; nt++)
#pragma unroll
            for (int e = 0; e < 4; e++) sc[nt][e] = 0.f;

#pragma unroll
        for (int ks = 0; ks < 4; ks++) {
            const uint32_t kso = (uint32_t)(ks * 16) * 2;
#pragma unroll
            for (int np = 0; np < 2; np++) {
                uint32_t kh4[2][4], kl4[2][4];
#pragma unroll
                for (int q2 = 0; q2 < 2; q2++) {
                    const uint32_t ro =
                        (uint32_t)(((np * 2 + q2) * 16) * ASTR) * 2;
                    ldsm_x4(kh4[q2], uKH + bfrag_off + ro + kso);
                    ldsm_x4(kl4[q2], uKL + bfrag_off + ro + kso);
                }
#pragma unroll
                for (int q2 = 0; q2 < 2; q2++) {
                    const int nt = (np * 2 + q2) * 2;
                    mma16816(sc[nt],     qfh[ks], kh4[q2][0], kh4[q2][1]);
                    mma16816(sc[nt + 1], qfh[ks], kh4[q2][2], kh4[q2][3]);
                }
#pragma unroll
                for (int q2 = 0; q2 < 2; q2++) {
                    const int nt = (np * 2 + q2) * 2;
                    mma16816(sc[nt],     qfl[ks], kh4[q2][0], kh4[q2][1]);
                    mma16816(sc[nt + 1], qfl[ks], kh4[q2][2], kh4[q2][3]);
                }
#pragma unroll
                for (int q2 = 0; q2 < 2; q2++) {
                    const int nt = (np * 2 + q2) * 2;
                    mma16816(sc[nt],     qfh[ks], kl4[q2][0], kl4[q2][1]);
                    mma16816(sc[nt + 1], qfh[ks], kl4[q2][2], kl4[q2][3]);
                }
            }
        }

        if (kt >= 2 * qt) {
#pragma unroll
            for (int nt = 0; nt < 8; nt++) {
                const int c0 = kt * 64 + nt * 8 + 2 * t;
                if (c0 > row0)     sc[nt][0] = -1e30f;
                if (c0 + 1 > row0) sc[nt][1] = -1e30f;
                if (c0 > row1)     sc[nt][2] = -1e30f;
                if (c0 + 1 > row1) sc[nt][3] = -1e30f;
            }
        }

        float mx0 = -1e30f, mx1 = -1e30f;
#pragma unroll
        for (int nt = 0; nt < 8; nt++) {
            mx0 = fmaxf(mx0, fmaxf(sc[nt][0], sc[nt][1]));
            mx1 = fmaxf(mx1, fmaxf(sc[nt][2], sc[nt][3]));
        }
        mx0 = fmaxf(mx0, __shfl_xor_sync(0xffffffffu, mx0, 1));
        mx0 = fmaxf(mx0, __shfl_xor_sync(0xffffffffu, mx0, 2));
        mx1 = fmaxf(mx1, __shfl_xor_sync(0xffffffffu, mx1, 1));
        mx1 = fmaxf(mx1, __shfl_xor_sync(0xffffffffu, mx1, 2));

        const float mn0 = fmaxf(m0, mx0), mn1 = fmaxf(m1, mx1);
        const float a0 = exp2p(m0 - mn0), a1 = exp2p(m1 - mn1);
        m0 = mn0; m1 = mn1;

        float rs0 = 0.f, rs1 = 0.f;
#pragma unroll
        for (int nt = 0; nt < 8; nt++) {
            sc[nt][0] = exp2p(sc[nt][0] - mn0);
            sc[nt][1] = exp2p(sc[nt][1] - mn0);
            sc[nt][2] = exp2p(sc[nt][2] - mn1);
            sc[nt][3] = exp2p(sc[nt][3] - mn1);
            rs0 += sc[nt][0] + sc[nt][1];
            rs1 += sc[nt][2] + sc[nt][3];
        }
        rs0 += __shfl_xor_sync(0xffffffffu, rs0, 1);
        rs0 += __shfl_xor_sync(0xffffffffu, rs0, 2);
        rs1 += __shfl_xor_sync(0xffffffffu, rs1, 1);
        rs1 += __shfl_xor_sync(0xffffffffu, rs1, 2);
        l0 = l0 * a0 + rs0;
        l1 = l1 * a1 + rs1;

#pragma unroll
        for (int nt = 0; nt < 8; nt++) {
            o[nt][0] *= a0; o[nt][1] *= a0;
            o[nt][2] *= a1; o[nt][3] *= a1;
        }

        uint32_t pfh[4][4], pfl[4][4];
#pragma unroll
        for (int ks = 0; ks < 4; ks++) {
            const float* p0 = sc[2 * ks];
            const float* p1 = sc[2 * ks + 1];
            pfh[ks][0] = pack_bf16x2(p0[0], p0[1]);
            pfh[ks][1] = pack_bf16x2(p0[2], p0[3]);
            pfh[ks][2] = pack_bf16x2(p1[0], p1[1]);
            pfh[ks][3] = pack_bf16x2(p1[2], p1[3]);
            pfl[ks][0] = pack_bf16x2(bf16_resid(p0[0]), bf16_resid(p0[1]));
            pfl[ks][1] = pack_bf16x2(bf16_resid(p0[2]), bf16_resid(p0[3]));
            pfl[ks][2] = pack_bf16x2(bf16_resid(p1[0]), bf16_resid(p1[1]));
            pfl[ks][3] = pack_bf16x2(bf16_resid(p1[2]), bf16_resid(p1[3]));
        }

#pragma unroll
        for (int ks = 0; ks < 4; ks++) {
            const uint32_t kso = (uint32_t)(ks * 16) * 2;
#pragma unroll
            for (int np = 0; np < 2; np++) {
                uint32_t vh4[2][4], vl4[2][4];
#pragma unroll
                for (int q2 = 0; q2 < 2; q2++) {
                    const uint32_t ro =
                        (uint32_t)(((np * 2 + q2) * 16) * ASTR) * 2;
                    ldsm_x4(vh4[q2], uVH + bfrag_off + ro + kso);
                    ldsm_x4(vl4[q2], uVL + bfrag_off + ro + kso);
                }
#pragma unroll
                for (int q2 = 0; q2 < 2; q2++) {
                    const int nt = (np * 2 + q2) * 2;
                    mma16816(o[nt],     pfh[ks], vh4[q2][0], vh4[q2][1]);
                    mma16816(o[nt + 1], pfh[ks], vh4[q2][2], vh4[q2][3]);
                }
#pragma unroll
                for (int q2 = 0; q2 < 2; q2++) {
                    const int nt = (np * 2 + q2) * 2;
                    mma16816(o[nt],     pfl[ks], vh4[q2][0], vh4[q2][1]);
                    mma16816(o[nt + 1], pfl[ks], vh4[q2][2], vh4[q2][3]);
                }
#pragma unroll
                for (int q2 = 0; q2 < 2; q2++) {
                    const int nt = (np * 2 + q2) * 2;
                    mma16816(o[nt],     pfh[ks], vl4[q2][0], vl4[q2][1]);
                    mma16816(o[nt + 1], pfh[ks], vl4[q2][2], vl4[q2][3]);
                }
            }
        }
    }

    // ---- epilogue: y = O / l as fp16 [b][s][h*64+d]
    const float inv0 = 1.0f / l0, inv1 = 1.0f / l1;
    const int b = bh >> 4, h = bh & 15;
#pragma unroll
    for (int nt = 0; nt < 8; nt++) {
        const int e = h * 64 + nt * 8 + 2 * t;
        {
            const size_t off = ((size_t)b * S_ + row0) * E_ + e;
            *(uint32_t*)(g_yh + off) =
                pack_f16x2(o[nt][0] * inv0, o[nt][1] * inv0);
        }
        {
            const size_t off = ((size_t)b * S_ + row1) * E_ + e;
            *(uint32_t*)(g_yh + off) =
                pack_f16x2(o[nt][2] * inv1, o[nt][3] * inv1);
        }
    }
}

// ---------------------------------------------------------------------------
// Launch
// ---------------------------------------------------------------------------
extern "C" void kernel_launch(void* const* d_in, const int* in_sizes, int n_in,
                              void* d_out, int out_size)
{
    const float* x      = (const float*)d_in[0];
    const float* W_kqv  = (const float*)d_in[1];
    const float* b_kqv  = (const float*)d_in[2];
    const float* W_proj = (const float*)d_in[3];
    const float* b_proj = (const float*)d_in[4];
    float* out = (float*)d_out;

    void *xh, *xl, *wkh, *wkl, *wph, *wpl, *yh;
    cudaGetSymbolAddress(&xh, g_xh);   cudaGetSymbolAddress(&xl, g_xl);
    cudaGetSymbolAddress(&wkh, g_wkh); cudaGetSymbolAddress(&wkl, g_wkl);
    cudaGetSymbolAddress(&wph, g_wph); cudaGetSymbolAddress(&wpl, g_wpl);
    cudaGetSymbolAddress(&yh, g_yh);

    cudaFuncSetAttribute(gemm_qkv, cudaFuncAttributeMaxDynamicSharedMemorySize, GSMEM);
    cudaFuncSetAttribute(gemm_proj, cudaFuncAttributeMaxDynamicSharedMemorySize, PSMEM);
    cudaFuncSetAttribute(attn_mma, cudaFuncAttributeMaxDynamicSharedMemorySize, ASMEM);

    // 0) splits
    {
        int n4 = M_ * E_ / 4;
        split_kernel<<<(n4 + 255) / 256, 256>>>(
            x, (__nv_bfloat16*)xh, (__nv_bfloat16*)xl, n4);
        n4 = NKQV * E_ / 4;
        split_kernel<<<(n4 + 255) / 256, 256>>>(
            W_kqv, (__nv_bfloat16*)wkh, (__nv_bfloat16*)wkl, n4);
        n4 = E_ * E_ / 4;
        splitH_kernel<<<(n4 + 255) / 256, 256>>>(
            W_proj, (__half*)wph, (__half*)wpl, n4);
    }

    // 1) QKV projection -> q/k/v bf16 hi/lo (q pre-scaled)
    gemm_qkv<<<dim3(NKQV / 128, M_ / 128), 128, GSMEM>>>(
        (const __nv_bfloat16*)xh, (const __nv_bfloat16*)xl,
        (const __nv_bfloat16*)wkh, (const __nv_bfloat16*)wkl,
        b_kqv, E_);

    // 2) V transpose [bh][s][d] -> [bh][d][s]
    vtrans_kernel<<<dim3(S_ / 64, B_ * H_), 256>>>();

    // 3) Tensor-core causal flash attention -> y fp16
    attn_mma<<<dim3(S_ / 128, B_ * H_), 256, ASMEM>>>();

    // 4) Output projection (fp16 2-MMA) -> d_out
    gemm_proj<<<dim3(E_ / 128, M_ / 128), 128, PSMEM>>>(
        (const __half*)yh, (const __half*)wph, (const __half*)wpl,
        b_proj, out, E_, E_);
}

// round 10
// speedup vs baseline: 1.5284x; 1.3469x over previous
#include <cuda_runtime.h>
#include <cuda_fp16.h>
#include <cstdint>
#include <math.h>

// Problem constants
constexpr int B_ = 4, S_ = 2048, E_ = 1024, H_ = 16, D_ = 64;
constexpr int M_ = B_ * S_;            // 8192 rows
constexpr int NKQV = 3 * E_;           // 3072

// ---------------------------------------------------------------------------
// Scratch (device globals; fp16). A-side operands: hi only. B-side: hi+lo.
// ---------------------------------------------------------------------------
__device__ __half g_xh[(size_t)M_ * E_];
__device__ __half g_wkh[(size_t)NKQV * E_], g_wkl[(size_t)NKQV * E_];
__device__ __half g_wph[(size_t)E_ * E_],  g_wpl[(size_t)E_ * E_];
__device__ __half g_qh[(size_t)B_*H_*S_*D_];
__device__ __half g_kh[(size_t)B_*H_*S_*D_], g_kl[(size_t)B_*H_*S_*D_];
__device__ __half g_vh[(size_t)B_*H_*S_*D_], g_vl[(size_t)B_*H_*S_*D_];
__device__ __half g_vth[(size_t)B_*H_*S_*D_], g_vtl[(size_t)B_*H_*S_*D_];
__device__ __half g_yh[(size_t)M_ * E_];

// ---------------------------------------------------------------------------
// helpers
// ---------------------------------------------------------------------------
__device__ __forceinline__ uint32_t pack_f16x2(float a, float b) {
    __half2 h = __floats2half2_rn(a, b);
    return *(uint32_t*)&h;
}
__device__ __forceinline__ float f16_resid(float a) {
    return a - __half2float(__float2half_rn(a));
}

__device__ __forceinline__ void mma16816h(float* c, const uint32_t* a,
                                          uint32_t b0, uint32_t b1) {
    asm volatile(
        "mma.sync.aligned.m16n8k16.row.col.f32.f16.f16.f32 "
        "{%0,%1,%2,%3}, {%4,%5,%6,%7}, {%8,%9}, {%0,%1,%2,%3};"
        : "+f"(c[0]), "+f"(c[1]), "+f"(c[2]), "+f"(c[3])
        : "r"(a[0]), "r"(a[1]), "r"(a[2]), "r"(a[3]), "r"(b0), "r"(b1));
}

__device__ __forceinline__ void ldsm_x4(uint32_t* r, uint32_t addr) {
    asm volatile(
        "ldmatrix.sync.aligned.m8n8.x4.shared.b16 {%0,%1,%2,%3}, [%4];"
        : "=r"(r[0]), "=r"(r[1]), "=r"(r[2]), "=r"(r[3]) : "r"(addr));
}

__device__ __forceinline__ uint32_t smem_u32(const void* p) {
    uint32_t a;
    asm("{ .reg .u64 t; cvta.to.shared.u64 t, %1; cvt.u32.u64 %0, t; }"
        : "=r"(a) : "l"(p));
    return a;
}
__device__ __forceinline__ void cp16(uint32_t dst, const void* src) {
    asm volatile("cp.async.ca.shared.global [%0], [%1], 16;"
                 :: "r"(dst), "l"(src));
}
#define CP_COMMIT() asm volatile("cp.async.commit_group;" ::: "memory")
#define CP_WAIT1()  asm volatile("cp.async.wait_group 1;" ::: "memory")
#define CP_WAIT0()  asm volatile("cp.async.wait_group 0;" ::: "memory")

// FMA-pipe exp2 (input in log2 units). ~2e-6 rel err.
__device__ __forceinline__ float exp2p(float x) {
    x = fmaxf(x, -80.f);
    float t = x + 12582912.f;
    int n = __float_as_int(t) - 0x4B400000;
    float r = x - (t - 12582912.f);
    float p = 1.33335581e-3f;
    p = fmaf(p, r, 9.61812911e-3f);
    p = fmaf(p, r, 5.55041087e-2f);
    p = fmaf(p, r, 2.40226507e-1f);
    p = fmaf(p, r, 6.93147180e-1f);
    p = fmaf(p, r, 1.0f);
    return p * __int_as_float((n + 127) << 23);
}

constexpr float QSCALE = 0.125f * 1.44269504088896340736f;

// ---------------------------------------------------------------------------
// conversions
// ---------------------------------------------------------------------------
__global__ void convH_kernel(const float* __restrict__ src,
                             __half* __restrict__ hi, int n4) {
    int i = blockIdx.x * blockDim.x + threadIdx.x;
    if (i >= n4) return;
    float4 v = ((const float4*)src)[i];
    ((uint2*)hi)[i] = make_uint2(pack_f16x2(v.x, v.y), pack_f16x2(v.z, v.w));
}

__global__ void splitH_kernel(const float* __restrict__ src,
                              __half* __restrict__ hi,
                              __half* __restrict__ lo, int n4) {
    int i = blockIdx.x * blockDim.x + threadIdx.x;
    if (i >= n4) return;
    float4 v = ((const float4*)src)[i];
    ((uint2*)hi)[i] = make_uint2(pack_f16x2(v.x, v.y), pack_f16x2(v.z, v.w));
    ((uint2*)lo)[i] = make_uint2(
        pack_f16x2(f16_resid(v.x), f16_resid(v.y)),
        pack_f16x2(f16_resid(v.z), f16_resid(v.w)));
}

// ---------------------------------------------------------------------------
// GEMM (fp16 2-MMA): C = Ah @ (Bh+Bl)^T + bias.
// 128x128x32 tiles, 4 warps of 64x64, 128 threads, 2-stage, 2 CTAs/SM.
// MODE 0: fp32 row-major out.  MODE 1: scatter q (hi) / k,v (hi+lo).
// ---------------------------------------------------------------------------
constexpr int GBK = 32;
constexpr int GSTR = 40;
constexpr int GTILE_E = 128 * GSTR;          // 5120
constexpr int PSTAGE_E = 3 * GTILE_E;        // Ah, Bh, Bl
constexpr int PSMEM = 2 * PSTAGE_E * 2;      // 61440 B

template <int MODE>
__global__ __launch_bounds__(128, 2) void gemm_h2(
    const __half* __restrict__ Ah,
    const __half* __restrict__ Bh, const __half* __restrict__ Bl,
    const float* __restrict__ bias, float* __restrict__ C, int N, int K)
{
    extern __shared__ __half smh[];
    const uint32_t smb_u = smem_u32(smh);
    const int tid = threadIdx.x;
    const int lane = tid & 31;
    const int w = tid >> 5;
    const int wm = w & 1, wn = w >> 1;
    const int g = lane >> 2, t = lane & 3;
    const int m0 = blockIdx.y * 128;
    const int n0 = blockIdx.x * 128;

    const __half* bases[3] = {
        Ah + (size_t)m0 * K, Bh + (size_t)n0 * K, Bl + (size_t)n0 * K };

    const int nsteps = K / GBK;

    auto issue = [&](int s) {
        __half* st = smh + (s & 1) * PSTAGE_E;
        const int k0 = s * GBK;
#pragma unroll
        for (int c = 0; c < 12; c++) {
            int ci = tid + c * 128;
            int arr = ci >> 9;
            int idx = ci & 511;
            int r = idx >> 2, ch = idx & 3;
            cp16(smem_u32(st + arr * GTILE_E + r * GSTR + ch * 8),
                 bases[arr] + (size_t)r * K + k0 + ch * 8);
        }
        CP_COMMIT();
    };

    const uint32_t a_off =
        (uint32_t)((wm * 64 + (lane & 15)) * GSTR + (lane >> 4) * 8) * 2;
    const uint32_t b_off =
        (uint32_t)((wn * 64 + ((lane >> 4) & 1) * 8 + (lane & 7)) * GSTR +
                   ((lane >> 3) & 1) * 8) * 2;

    float acc[4][8][4];
#pragma unroll
    for (int i = 0; i < 4; i++)
#pragma unroll
        for (int j = 0; j < 8; j++)
#pragma unroll
            for (int e = 0; e < 4; e++) acc[i][j][e] = 0.f;

    issue(0);
    issue(1);

    for (int s = 0; s < nsteps; s++) {
        if (s + 1 < nsteps) { CP_WAIT1(); } else { CP_WAIT0(); }
        __syncthreads();

        const uint32_t st = smb_u + (uint32_t)((s & 1) * PSTAGE_E) * 2;
        const uint32_t uAh = st;
        const uint32_t uBh = st + GTILE_E * 2;
        const uint32_t uBl = st + 2 * GTILE_E * 2;

#pragma unroll
        for (int ks = 0; ks < 2; ks++) {
            const uint32_t kso = (uint32_t)(ks * 16) * 2;
            uint32_t ah[4][4];
#pragma unroll
            for (int mt = 0; mt < 4; mt++) {
                const uint32_t ro = (uint32_t)(mt * 16 * GSTR) * 2;
                ldsm_x4(ah[mt], uAh + a_off + ro + kso);
            }
#pragma unroll
            for (int pp = 0; pp < 2; pp++) {
                uint32_t bh[2][4], bl[2][4];
#pragma unroll
                for (int q2 = 0; q2 < 2; q2++) {
                    const uint32_t ro =
                        (uint32_t)(((pp * 2 + q2) * 16) * GSTR) * 2;
                    ldsm_x4(bh[q2], uBh + b_off + ro + kso);
                    ldsm_x4(bl[q2], uBl + b_off + ro + kso);
                }
#pragma unroll
                for (int q2 = 0; q2 < 2; q2++) {
                    const int nt = (pp * 2 + q2) * 2;
#pragma unroll
                    for (int mt = 0; mt < 4; mt++) {
                        mma16816h(acc[mt][nt],     ah[mt], bh[q2][0], bh[q2][1]);
                        mma16816h(acc[mt][nt + 1], ah[mt], bh[q2][2], bh[q2][3]);
                    }
                }
#pragma unroll
                for (int q2 = 0; q2 < 2; q2++) {
                    const int nt = (pp * 2 + q2) * 2;
#pragma unroll
                    for (int mt = 0; mt < 4; mt++) {
                        mma16816h(acc[mt][nt],     ah[mt], bl[q2][0], bl[q2][1]);
                        mma16816h(acc[mt][nt + 1], ah[mt], bl[q2][2], bl[q2][3]);
                    }
                }
            }
        }

        __syncthreads();
        if (s + 2 < nsteps) issue(s + 2);
    }

    // ---- epilogue --------------------------------------------------------
#pragma unroll
    for (int mt = 0; mt < 4; mt++) {
#pragma unroll
        for (int nt = 0; nt < 8; nt++) {
            const int m = m0 + wm * 64 + mt * 16 + g;
            const int n = n0 + wn * 64 + nt * 8 + t * 2;
            const float* c = acc[mt][nt];
            float2 bv = *(const float2*)(bias + n);
            if (MODE == 0) {
                *(float2*)(C + (size_t)m * N + n) =
                    make_float2(c[0] + bv.x, c[1] + bv.y);
                *(float2*)(C + (size_t)(m + 8) * N + n) =
                    make_float2(c[2] + bv.x, c[3] + bv.y);
            } else {
                const int which = n >> 10;
                const int h = (n >> 6) & 15;
                const int d = n & 63;
#pragma unroll
                for (int rr = 0; rr < 2; rr++) {
                    const int mm = m + rr * 8;
                    const int b = mm >> 11, s = mm & 2047;
                    const size_t off =
                        ((((size_t)b * H_ + h) * S_) + s) * D_ + d;
                    float v0 = c[rr * 2 + 0] + bv.x;
                    float v1 = c[rr * 2 + 1] + bv.y;
                    if (which == 1) {       // q: hi only, pre-scaled
                        *(uint32_t*)(g_qh + off) =
                            pack_f16x2(v0 * QSCALE, v1 * QSCALE);
                    } else {
                        __half* dh = (which == 0) ? g_kh : g_vh;
                        __half* dl = (which == 0) ? g_kl : g_vl;
                        *(uint32_t*)(dh + off) = pack_f16x2(v0, v1);
                        *(uint32_t*)(dl + off) =
                            pack_f16x2(f16_resid(v0), f16_resid(v1));
                    }
                }
            }
        }
    }
}

// ---------------------------------------------------------------------------
// V transpose: [bh][s][d] -> [bh][d][s], hi and lo (fp16)
// ---------------------------------------------------------------------------
__global__ __launch_bounds__(256) void vtrans_kernel() {
    __shared__ __half tile[64][72];
    const int tid = threadIdx.x;
    const int st = blockIdx.x;
    const int bh = blockIdx.y;

    const __half* srcs[2] = {
        g_vh + ((size_t)bh * S_ + st * 64) * D_,
        g_vl + ((size_t)bh * S_ + st * 64) * D_ };
    __half* dsts[2] = {
        g_vth + (size_t)bh * D_ * S_ + st * 64,
        g_vtl + (size_t)bh * D_ * S_ + st * 64 };

    for (int a = 0; a < 2; a++) {
        __syncthreads();
#pragma unroll
        for (int c = 0; c < 8; c++) {
            int ci = tid + c * 256;
            int r = ci >> 5, ch = ci & 31;
            *(uint32_t*)&tile[r][ch * 2] =
                *(const uint32_t*)(srcs[a] + (size_t)r * D_ + ch * 2);
        }
        __syncthreads();
#pragma unroll
        for (int c = 0; c < 8; c++) {
            int ci = tid + c * 256;
            int d = ci >> 5, s2 = (ci & 31) * 2;
            __half2 o = __halves2half2(tile[s2][d], tile[s2 + 1][d]);
            *(uint32_t*)(dsts[a] + (size_t)d * S_ + s2) = *(uint32_t*)&o;
        }
    }
}

// ---------------------------------------------------------------------------
// Tensor-core causal flash attention, fp16 2-MMA scheme.
// CTA = (q-tile 128, bh), 8 warps, 2-stage KV ring, 2 CTAs/SM.
// S = Qh @ (Kh+Kl)^T;  O += Ph @ (Vh+Vl)  (P hi only).
// ---------------------------------------------------------------------------
constexpr int ASTR = 72;
constexpr int AQ_E = 128 * ASTR;                // q hi staging only
constexpr int AKT_E = 64 * ASTR;
constexpr int AKSTAGE_E = 4 * AKT_E;            // kh,kl,vth,vtl
constexpr int ASMEM = (AQ_E + 2 * AKSTAGE_E) * 2;   // 92160 B -> 2 CTAs/SM

__global__ __launch_bounds__(256, 2) void attn_mma() {
    extern __shared__ __half sma[];
    const uint32_t sma_u = smem_u32(sma);
    const int tid = threadIdx.x;
    const int lane = tid & 31;
    const int w = tid >> 5;
    const int g = lane >> 2, t = lane & 3;
    const int qt = (S_ / 128 - 1) - blockIdx.x;
    const int bh = blockIdx.y;
    const int nkt = 2 * qt + 2;

    __half* QH = sma;
    const uint32_t KV0_u = sma_u + AQ_E * 2;

    // ---- stage Q (hi only): 128 rows x 64 cols = 1024 16B chunks
    {
        const __half* qsrc = g_qh + ((size_t)bh * S_ + qt * 128) * D_;
#pragma unroll
        for (int c = 0; c < 4; c++) {
            int ci = tid + c * 256;
            int r = ci >> 3, ch = ci & 7;
            cp16(smem_u32(sma + r * ASTR + ch * 8),
                 qsrc + (size_t)r * D_ + ch * 8);
        }
        CP_COMMIT();
    }

    auto issueKV = [&](int kt) {
        uint32_t st = KV0_u + (uint32_t)((kt & 1) * AKSTAGE_E) * 2;
        const __half* bases[4] = {
            g_kh + ((size_t)bh * S_ + kt * 64) * D_,
            g_kl + ((size_t)bh * S_ + kt * 64) * D_,
            g_vth + (size_t)bh * D_ * S_ + kt * 64,
            g_vtl + (size_t)bh * D_ * S_ + kt * 64 };
#pragma unroll
        for (int c = 0; c < 8; c++) {
            int ci = tid + c * 256;
            int arr = ci >> 9;
            int idx = ci & 511;
            int r = idx >> 3, ch = idx & 7;
            const size_t rs = (arr < 2) ? (size_t)D_ : (size_t)S_;
            cp16(st + (uint32_t)(arr * AKT_E + r * ASTR + ch * 8) * 2,
                 bases[arr] + (size_t)r * rs + ch * 8);
        }
        CP_COMMIT();
    };

    issueKV(0);
    CP_WAIT1();            // Q complete
    __syncthreads();

    // ---- Q fragments (hi only; registers for CTA lifetime)
    uint32_t qfh[4][4];
#pragma unroll
    for (int ks = 0; ks < 4; ks++) {
        const int kb = ks * 16 + t * 2;
        const int r0 = (w * 16 + g) * ASTR;
        qfh[ks][0] = *(const uint32_t*)(QH + r0 + kb);
        qfh[ks][1] = *(const uint32_t*)(QH + r0 + 8 * ASTR + kb);
        qfh[ks][2] = *(const uint32_t*)(QH + r0 + kb + 8);
        qfh[ks][3] = *(const uint32_t*)(QH + r0 + 8 * ASTR + kb + 8);
    }

    const uint32_t bfrag_off =
        (uint32_t)((((lane >> 4) & 1) * 8 + (lane & 7)) * ASTR +
                   ((lane >> 3) & 1) * 8) * 2;

    float o[8][4];
#pragma unroll
    for (int nt = 0; nt < 8; nt++)
#pragma unroll
        for (int e = 0; e < 4; e++) o[nt][e] = 0.f;
    float m0 = -1e30f, m1 = -1e30f, l0 = 0.f, l1 = 0.f;

    const int row0 = qt * 128 + w * 16 + g;
    const int row1 = row0 + 8;

    for (int kt = 0; kt < nkt; kt++) {
        CP_WAIT0();
        __syncthreads();
        if (kt + 1 < nkt) issueKV(kt + 1);

        // fully-masked warp on the diagonal k-tile: skip all MMAs
        if (kt * 64 > qt * 128 + w * 16 + 15) continue;

        const uint32_t st = KV0_u + (uint32_t)((kt & 1) * AKSTAGE_E) * 2;
        const uint32_t uKH = st;
        const uint32_t uKL = st + AKT_E * 2;
        const uint32_t uVH = st + 2 * AKT_E * 2;
        const uint32_t uVL = st + 3 * AKT_E * 2;

        // ---- S = Qh @ (Kh+Kl)^T
        float sc[8][4];
#pragma unroll
        for (int nt = 0; nt < 8; nt++)
#pragma unroll
            for (int e = 0; e < 4; e++) sc[nt][e] = 0.f;

#pragma unroll
        for (int ks = 0; ks < 4; ks++) {
            const uint32_t kso = (uint32_t)(ks * 16) * 2;
#pragma unroll
            for (int np = 0; np < 2; np++) {
                uint32_t kh4[2][4], kl4[2][4];
#pragma unroll
                for (int q2 = 0; q2 < 2; q2++) {
                    const uint32_t ro =
                        (uint32_t)(((np * 2 + q2) * 16) * ASTR) * 2;
                    ldsm_x4(kh4[q2], uKH + bfrag_off + ro + kso);
                    ldsm_x4(kl4[q2], uKL + bfrag_off + ro + kso);
                }
#pragma unroll
                for (int q2 = 0; q2 < 2; q2++) {
                    const int nt = (np * 2 + q2) * 2;
                    mma16816h(sc[nt],     qfh[ks], kh4[q2][0], kh4[q2][1]);
                    mma16816h(sc[nt + 1], qfh[ks], kh4[q2][2], kh4[q2][3]);
                }
#pragma unroll
                for (int q2 = 0; q2 < 2; q2++) {
                    const int nt = (np * 2 + q2) * 2;
                    mma16816h(sc[nt],     qfh[ks], kl4[q2][0], kl4[q2][1]);
                    mma16816h(sc[nt + 1], qfh[ks], kl4[q2][2], kl4[q2][3]);
                }
            }
        }

        // ---- causal mask
        if (kt >= 2 * qt) {
#pragma unroll
            for (int nt = 0; nt < 8; nt++) {
                const int c0 = kt * 64 + nt * 8 + 2 * t;
                if (c0 > row0)     sc[nt][0] = -1e30f;
                if (c0 + 1 > row0) sc[nt][1] = -1e30f;
                if (c0 > row1)     sc[nt][2] = -1e30f;
                if (c0 + 1 > row1) sc[nt][3] = -1e30f;
            }
        }

        // ---- online softmax (base-2, FMA pipe)
        float mx0 = -1e30f, mx1 = -1e30f;
#pragma unroll
        for (int nt = 0; nt < 8; nt++) {
            mx0 = fmaxf(mx0, fmaxf(sc[nt][0], sc[nt][1]));
            mx1 = fmaxf(mx1, fmaxf(sc[nt][2], sc[nt][3]));
        }
        mx0 = fmaxf(mx0, __shfl_xor_sync(0xffffffffu, mx0, 1));
        mx0 = fmaxf(mx0, __shfl_xor_sync(0xffffffffu, mx0, 2));
        mx1 = fmaxf(mx1, __shfl_xor_sync(0xffffffffu, mx1, 1));
        mx1 = fmaxf(mx1, __shfl_xor_sync(0xffffffffu, mx1, 2));

        const float mn0 = fmaxf(m0, mx0), mn1 = fmaxf(m1, mx1);
        const float a0 = exp2p(m0 - mn0), a1 = exp2p(m1 - mn1);
        m0 = mn0; m1 = mn1;

        float rs0 = 0.f, rs1 = 0.f;
#pragma unroll
        for (int nt = 0; nt < 8; nt++) {
            sc[nt][0] = exp2p(sc[nt][0] - mn0);
            sc[nt][1] = exp2p(sc[nt][1] - mn0);
            sc[nt][2] = exp2p(sc[nt][2] - mn1);
            sc[nt][3] = exp2p(sc[nt][3] - mn1);
            rs0 += sc[nt][0] + sc[nt][1];
            rs1 += sc[nt][2] + sc[nt][3];
        }
        rs0 += __shfl_xor_sync(0xffffffffu, rs0, 1);
        rs0 += __shfl_xor_sync(0xffffffffu, rs0, 2);
        rs1 += __shfl_xor_sync(0xffffffffu, rs1, 1);
        rs1 += __shfl_xor_sync(0xffffffffu, rs1, 2);
        l0 = l0 * a0 + rs0;
        l1 = l1 * a1 + rs1;

#pragma unroll
        for (int nt = 0; nt < 8; nt++) {
            o[nt][0] *= a0; o[nt][1] *= a0;
            o[nt][2] *= a1; o[nt][3] *= a1;
        }

        // ---- P fragments (fp16 hi only, FA layout)
        uint32_t pfh[4][4];
#pragma unroll
        for (int ks = 0; ks < 4; ks++) {
            const float* p0 = sc[2 * ks];
            const float* p1 = sc[2 * ks + 1];
            pfh[ks][0] = pack_f16x2(p0[0], p0[1]);
            pfh[ks][1] = pack_f16x2(p0[2], p0[3]);
            pfh[ks][2] = pack_f16x2(p1[0], p1[1]);
            pfh[ks][3] = pack_f16x2(p1[2], p1[3]);
        }

        // ---- O += Ph @ (Vh+Vl)
#pragma unroll
        for (int ks = 0; ks < 4; ks++) {
            const uint32_t kso = (uint32_t)(ks * 16) * 2;
#pragma unroll
            for (int np = 0; np < 2; np++) {
                uint32_t vh4[2][4], vl4[2][4];
#pragma unroll
                for (int q2 = 0; q2 < 2; q2++) {
                    const uint32_t ro =
                        (uint32_t)(((np * 2 + q2) * 16) * ASTR) * 2;
                    ldsm_x4(vh4[q2], uVH + bfrag_off + ro + kso);
                    ldsm_x4(vl4[q2], uVL + bfrag_off + ro + kso);
                }
#pragma unroll
                for (int q2 = 0; q2 < 2; q2++) {
                    const int nt = (np * 2 + q2) * 2;
                    mma16816h(o[nt],     pfh[ks], vh4[q2][0], vh4[q2][1]);
                    mma16816h(o[nt + 1], pfh[ks], vh4[q2][2], vh4[q2][3]);
                }
#pragma unroll
                for (int q2 = 0; q2 < 2; q2++) {
                    const int nt = (np * 2 + q2) * 2;
                    mma16816h(o[nt],     pfh[ks], vl4[q2][0], vl4[q2][1]);
                    mma16816h(o[nt + 1], pfh[ks], vl4[q2][2], vl4[q2][3]);
                }
            }
        }
    }

    // ---- epilogue: y = O / l as fp16 [b][s][h*64+d]
    const float inv0 = 1.0f / l0, inv1 = 1.0f / l1;
    const int b = bh >> 4, h = bh & 15;
#pragma unroll
    for (int nt = 0; nt < 8; nt++) {
        const int e = h * 64 + nt * 8 + 2 * t;
        {
            const size_t off = ((size_t)b * S_ + row0) * E_ + e;
            *(uint32_t*)(g_yh + off) =
                pack_f16x2(o[nt][0] * inv0, o[nt][1] * inv0);
        }
        {
            const size_t off = ((size_t)b * S_ + row1) * E_ + e;
            *(uint32_t*)(g_yh + off) =
                pack_f16x2(o[nt][2] * inv1, o[nt][3] * inv1);
        }
    }
}

// ---------------------------------------------------------------------------
// Launch
// ---------------------------------------------------------------------------
extern "C" void kernel_launch(void* const* d_in, const int* in_sizes, int n_in,
                              void* d_out, int out_size)
{
    const float* x      = (const float*)d_in[0];
    const float* W_kqv  = (const float*)d_in[1];
    const float* b_kqv  = (const float*)d_in[2];
    const float* W_proj = (const float*)d_in[3];
    const float* b_proj = (const float*)d_in[4];
    float* out = (float*)d_out;

    void *xh, *wkh, *wkl, *wph, *wpl, *yh;
    cudaGetSymbolAddress(&xh, g_xh);
    cudaGetSymbolAddress(&wkh, g_wkh); cudaGetSymbolAddress(&wkl, g_wkl);
    cudaGetSymbolAddress(&wph, g_wph); cudaGetSymbolAddress(&wpl, g_wpl);
    cudaGetSymbolAddress(&yh, g_yh);

    cudaFuncSetAttribute(gemm_h2<0>, cudaFuncAttributeMaxDynamicSharedMemorySize, PSMEM);
    cudaFuncSetAttribute(gemm_h2<1>, cudaFuncAttributeMaxDynamicSharedMemorySize, PSMEM);
    cudaFuncSetAttribute(attn_mma,  cudaFuncAttributeMaxDynamicSharedMemorySize, ASMEM);

    // 0) conversions
    {
        int n4 = M_ * E_ / 4;
        convH_kernel<<<(n4 + 255) / 256, 256>>>(x, (__half*)xh, n4);
        n4 = NKQV * E_ / 4;
        splitH_kernel<<<(n4 + 255) / 256, 256>>>(
            W_kqv, (__half*)wkh, (__half*)wkl, n4);
        n4 = E_ * E_ / 4;
        splitH_kernel<<<(n4 + 255) / 256, 256>>>(
            W_proj, (__half*)wph, (__half*)wpl, n4);
    }

    // 1) QKV projection -> q (hi) / k,v (hi+lo)
    gemm_h2<1><<<dim3(NKQV / 128, M_ / 128), 128, PSMEM>>>(
        (const __half*)xh, (const __half*)wkh, (const __half*)wkl,
        b_kqv, nullptr, NKQV, E_);

    // 2) V transpose [bh][s][d] -> [bh][d][s]
    vtrans_kernel<<<dim3(S_ / 64, B_ * H_), 256>>>();

    // 3) Tensor-core causal flash attention -> y fp16
    attn_mma<<<dim3(S_ / 128, B_ * H_), 256, ASMEM>>>();

    // 4) Output projection -> d_out
    gemm_h2<0><<<dim3(E_ / 128, M_ / 128), 128, PSMEM>>>(
        (const __half*)yh, (const __half*)wph, (const __half*)wpl,
        b_proj, out, E_, E_);
}